// round 1
// baseline (speedup 1.0000x reference)
#include <cuda_runtime.h>
#include <cuda_bf16.h>
#include <math.h>

// ---------------- Problem constants ----------------
#define V_SZ 50257
#define E_SZ 768
#define H_SZ 12
#define L_SZ 6
#define T_SZ 1024
#define B_SZ 2
#define D_SZ 64
#define BT   (B_SZ * T_SZ)      // 2048
#define FF   (4 * E_SZ)         // 3072

// ---------------- Scratch (device globals; no allocations allowed) ----------
__device__ float g_x  [BT * E_SZ];
__device__ float g_h  [BT * E_SZ];
__device__ float g_q  [BT * E_SZ];
__device__ float g_k  [BT * E_SZ];
__device__ float g_v  [BT * E_SZ];
__device__ float g_att[BT * E_SZ];
__device__ float g_m1 [BT * FF];

// ---------------- Embedding: x = wte[tok] + wpe[t] ----------------
__global__ void embed_kernel(const int* __restrict__ tok,
                             const float* __restrict__ wte,
                             const float* __restrict__ wpe,
                             float* __restrict__ x) {
    int row = blockIdx.x;            // 0..BT-1
    int t   = row % T_SZ;
    int tk  = tok[row];
    int e   = threadIdx.x * 4;       // 192 threads * 4 = 768
    const float4 a = *(const float4*)(wte + (size_t)tk * E_SZ + e);
    const float4 b = *(const float4*)(wpe + (size_t)t  * E_SZ + e);
    float4 o;
    o.x = a.x + b.x; o.y = a.y + b.y; o.z = a.z + b.z; o.w = a.w + b.w;
    *(float4*)(x + (size_t)row * E_SZ + e) = o;
}

// ---------------- LayerNorm (one block = one row of 768) ----------------
__global__ void layernorm_kernel(const float* __restrict__ x,
                                 const float* __restrict__ sc,
                                 const float* __restrict__ bi,
                                 float* __restrict__ out) {
    int row = blockIdx.x;
    const float* xr = x + (size_t)row * E_SZ;
    float lv[3];
    float s = 0.f, sq = 0.f;
#pragma unroll
    for (int i = 0; i < 3; i++) {
        float t = xr[threadIdx.x + i * 256];
        lv[i] = t; s += t; sq += t * t;
    }
    // block reduction (8 warps)
#pragma unroll
    for (int o = 16; o > 0; o >>= 1) {
        s  += __shfl_down_sync(0xffffffffu, s,  o);
        sq += __shfl_down_sync(0xffffffffu, sq, o);
    }
    __shared__ float sa[8], sb[8];
    int w = threadIdx.x >> 5, lane = threadIdx.x & 31;
    if (lane == 0) { sa[w] = s; sb[w] = sq; }
    __syncthreads();
    __shared__ float s_mu, s_rstd;
    if (threadIdx.x == 0) {
        float ts = 0.f, tq = 0.f;
#pragma unroll
        for (int i = 0; i < 8; i++) { ts += sa[i]; tq += sb[i]; }
        float mu  = ts * (1.0f / E_SZ);
        float var = tq * (1.0f / E_SZ) - mu * mu;
        s_mu = mu;
        s_rstd = rsqrtf(var + 1e-5f);
    }
    __syncthreads();
    float mu = s_mu, rstd = s_rstd;
#pragma unroll
    for (int i = 0; i < 3; i++) {
        int c = threadIdx.x + i * 256;
        out[(size_t)row * E_SZ + c] = (lv[i] - mu) * rstd * sc[c] + bi[c];
    }
}

// ---------------- SGEMM 128x128x8, 8x8 per thread ----------------
// C[M,N] = A[M,K] @ B  (+bias +gelu +residual per epi flags)
// TRANSB=false: B is [K,N] row-major.  TRANSB=true: B is [N,K] row-major.
// epi bit0: add bias[col]; bit1: GELU(exact); bit2: add resid[r,c]
__device__ __forceinline__ float gelu_exact(float v) {
    return 0.5f * v * (1.0f + erff(v * 0.70710678118654752f));
}

template <bool TRANSB>
__global__ __launch_bounds__(256)
void sgemm_kernel(const float* __restrict__ A, const float* __restrict__ Bm,
                  const float* __restrict__ bias, const float* __restrict__ resid,
                  float* __restrict__ C, int M, int N, int K, int epi) {
    __shared__ float As[8][128];
    __shared__ float Bs[8][128];
    const int tid = threadIdx.x;
    const int tx = tid & 15, ty = tid >> 4;
    const int bm = blockIdx.y * 128, bn = blockIdx.x * 128;

    float acc[8][8];
#pragma unroll
    for (int i = 0; i < 8; i++)
#pragma unroll
        for (int j = 0; j < 8; j++) acc[i][j] = 0.f;

    const int aRow = tid >> 1, aCol = (tid & 1) * 4;   // A tile 128x8
    int bRow, bCol;
    if (TRANSB) { bRow = tid >> 1; bCol = (tid & 1) * 4; }   // B tile rows=n(128), cols=k(8)
    else        { bRow = tid >> 5; bCol = (tid & 31) * 4; }  // B tile rows=k(8), cols=n(128)

    for (int k0 = 0; k0 < K; k0 += 8) {
        {
            int gm = bm + aRow;
            float4 v = make_float4(0.f, 0.f, 0.f, 0.f);
            if (gm < M) v = *(const float4*)(A + (size_t)gm * K + k0 + aCol);
            As[aCol + 0][aRow] = v.x; As[aCol + 1][aRow] = v.y;
            As[aCol + 2][aRow] = v.z; As[aCol + 3][aRow] = v.w;
        }
        if (TRANSB) {
            int gn = bn + bRow;
            float4 v = make_float4(0.f, 0.f, 0.f, 0.f);
            if (gn < N) v = *(const float4*)(Bm + (size_t)gn * K + k0 + bCol);
            Bs[bCol + 0][bRow] = v.x; Bs[bCol + 1][bRow] = v.y;
            Bs[bCol + 2][bRow] = v.z; Bs[bCol + 3][bRow] = v.w;
        } else {
            int gn = bn + bCol;
            float4 v = make_float4(0.f, 0.f, 0.f, 0.f);
            const float* bp = Bm + (size_t)(k0 + bRow) * N + gn;
            if (gn + 3 < N) v = *(const float4*)bp;
            else {
                if (gn + 0 < N) v.x = bp[0];
                if (gn + 1 < N) v.y = bp[1];
                if (gn + 2 < N) v.z = bp[2];
            }
            Bs[bRow][bCol + 0] = v.x; Bs[bRow][bCol + 1] = v.y;
            Bs[bRow][bCol + 2] = v.z; Bs[bRow][bCol + 3] = v.w;
        }
        __syncthreads();
#pragma unroll
        for (int kk = 0; kk < 8; kk++) {
            float a[8], b[8];
#pragma unroll
            for (int i = 0; i < 4; i++) {
                a[i]     = As[kk][ty * 4 + i];
                a[4 + i] = As[kk][64 + ty * 4 + i];
                b[i]     = Bs[kk][tx * 4 + i];
                b[4 + i] = Bs[kk][64 + tx * 4 + i];
            }
#pragma unroll
            for (int i = 0; i < 8; i++)
#pragma unroll
                for (int j = 0; j < 8; j++) acc[i][j] += a[i] * b[j];
        }
        __syncthreads();
    }

#pragma unroll
    for (int i = 0; i < 8; i++) {
        int r = bm + ((i < 4) ? (ty * 4 + i) : (64 + ty * 4 + (i - 4)));
        if (r >= M) continue;
#pragma unroll
        for (int j = 0; j < 8; j++) {
            int c = bn + ((j < 4) ? (tx * 4 + j) : (64 + tx * 4 + (j - 4)));
            if (c >= N) continue;
            float val = acc[i][j];
            if (epi & 1) val += bias[c];
            if (epi & 2) val = gelu_exact(val);
            if (epi & 4) val += resid[(size_t)r * N + c];
            C[(size_t)r * N + c] = val;
        }
    }
}

// ---------------- Causal attention, online softmax ----------------
// q,k,v laid out as (B,T,E) with head h occupying columns [h*64, h*64+64).
// grid: (T/128, B*H), block: 128 threads (one query per thread).
__global__ __launch_bounds__(128)
void attn_kernel(const float* __restrict__ q, const float* __restrict__ k,
                 const float* __restrict__ v, float* __restrict__ o) {
    const int bh = blockIdx.y;
    const int b  = bh / H_SZ, h = bh % H_SZ;
    const int qi = blockIdx.x * 128 + threadIdx.x;

    float qr[D_SZ];
    {
        const float* qp = q + ((size_t)(b * T_SZ + qi) * E_SZ) + h * D_SZ;
#pragma unroll
        for (int d = 0; d < D_SZ; d++) qr[d] = qp[d] * 0.125f;  // 1/sqrt(64)
    }
    float m = -1e30f, l = 0.f;
    float accv[D_SZ];
#pragma unroll
    for (int d = 0; d < D_SZ; d++) accv[d] = 0.f;

    __shared__ float Ks[64][D_SZ];
    __shared__ float Vs[64][D_SZ];

    const int qmax = blockIdx.x * 128 + 127;
    for (int kt = 0; kt <= qmax; kt += 64) {
        // cooperative load of 64x64 K and V tiles (1024 float4 each)
        for (int i = threadIdx.x; i < 64 * 16; i += 128) {
            int rr = i >> 4, cc = (i & 15) * 4;
            size_t base = ((size_t)(b * T_SZ + kt + rr) * E_SZ) + h * D_SZ + cc;
            float4 kv = *(const float4*)(k + base);
            Ks[rr][cc] = kv.x; Ks[rr][cc + 1] = kv.y; Ks[rr][cc + 2] = kv.z; Ks[rr][cc + 3] = kv.w;
            float4 vv = *(const float4*)(v + base);
            Vs[rr][cc] = vv.x; Vs[rr][cc + 1] = vv.y; Vs[rr][cc + 2] = vv.z; Vs[rr][cc + 3] = vv.w;
        }
        __syncthreads();
        int kend = qi - kt + 1;
        if (kend > 64) kend = 64;
        for (int kk = 0; kk < kend; kk++) {
            float s = 0.f;
#pragma unroll
            for (int d = 0; d < D_SZ; d++) s += qr[d] * Ks[kk][d];
            float mn = fmaxf(m, s);
            float c  = __expf(m - mn);
            float p  = __expf(s - mn);
            l = l * c + p;
#pragma unroll
            for (int d = 0; d < D_SZ; d++) accv[d] = accv[d] * c + p * Vs[kk][d];
            m = mn;
        }
        __syncthreads();
    }
    float inv = 1.f / l;
    float* op = o + ((size_t)(b * T_SZ + qi) * E_SZ) + h * D_SZ;
#pragma unroll
    for (int d = 0; d < D_SZ; d++) op[d] = accv[d] * inv;
}

// ---------------- Host-side orchestration ----------------
extern "C" void kernel_launch(void* const* d_in, const int* in_sizes, int n_in,
                              void* d_out, int out_size) {
    (void)in_sizes; (void)n_in; (void)out_size;
    const int*   tokens = (const int*)  d_in[0];
    const float* wte    = (const float*)d_in[1];
    const float* wpe    = (const float*)d_in[2];
    const float* Wq     = (const float*)d_in[3];
    const float* Wk     = (const float*)d_in[4];
    const float* Wv     = (const float*)d_in[5];
    const float* Wo     = (const float*)d_in[6];
    const float* bo     = (const float*)d_in[7];
    const float* ln1_s  = (const float*)d_in[8];
    const float* ln1_b  = (const float*)d_in[9];
    const float* W1     = (const float*)d_in[10];
    const float* b1     = (const float*)d_in[11];
    const float* W2     = (const float*)d_in[12];
    const float* b2     = (const float*)d_in[13];
    const float* ln2_s  = (const float*)d_in[14];
    const float* ln2_b  = (const float*)d_in[15];
    const float* lnf_s  = (const float*)d_in[16];
    const float* lnf_b  = (const float*)d_in[17];
    float* out = (float*)d_out;

    float *x, *h, *q, *k, *v, *att, *m1;
    cudaGetSymbolAddress((void**)&x,   g_x);
    cudaGetSymbolAddress((void**)&h,   g_h);
    cudaGetSymbolAddress((void**)&q,   g_q);
    cudaGetSymbolAddress((void**)&k,   g_k);
    cudaGetSymbolAddress((void**)&v,   g_v);
    cudaGetSymbolAddress((void**)&att, g_att);
    cudaGetSymbolAddress((void**)&m1,  g_m1);

    embed_kernel<<<BT, 192>>>(tokens, wte, wpe, x);

    const dim3 gE((E_SZ + 127) / 128, (BT + 127) / 128);   // 6 x 16
    const dim3 gF((FF + 127) / 128,  (BT + 127) / 128);    // 24 x 16

    for (int l = 0; l < L_SZ; l++) {
        const size_t wOff  = (size_t)l * E_SZ * E_SZ;
        const size_t w1Off = (size_t)l * E_SZ * FF;
        const size_t vOff  = (size_t)l * E_SZ;
        const size_t fOff  = (size_t)l * FF;

        layernorm_kernel<<<BT, 256>>>(x, ln1_s + vOff, ln1_b + vOff, h);
        sgemm_kernel<false><<<gE, 256>>>(h, Wq + wOff, nullptr, nullptr, q, BT, E_SZ, E_SZ, 0);
        sgemm_kernel<false><<<gE, 256>>>(h, Wk + wOff, nullptr, nullptr, k, BT, E_SZ, E_SZ, 0);
        sgemm_kernel<false><<<gE, 256>>>(h, Wv + wOff, nullptr, nullptr, v, BT, E_SZ, E_SZ, 0);
        attn_kernel<<<dim3(T_SZ / 128, B_SZ * H_SZ), 128>>>(q, k, v, att);
        sgemm_kernel<false><<<gE, 256>>>(att, Wo + wOff, bo + vOff, x, x, BT, E_SZ, E_SZ, 1 | 4);
        layernorm_kernel<<<BT, 256>>>(x, ln2_s + vOff, ln2_b + vOff, h);
        sgemm_kernel<false><<<gF, 256>>>(h, W1 + w1Off, b1 + fOff, nullptr, m1, BT, FF, E_SZ, 1 | 2);
        sgemm_kernel<false><<<gE, 256>>>(m1, W2 + w1Off, b2 + vOff, x, x, BT, E_SZ, FF, 1 | 4);
    }

    layernorm_kernel<<<BT, 256>>>(x, lnf_s, lnf_b, h);
    sgemm_kernel<true><<<dim3((V_SZ + 127) / 128, (BT + 127) / 128), 256>>>(
        h, wte, nullptr, nullptr, out, BT, V_SZ, E_SZ, 0);
}

// round 3
// speedup vs baseline: 1.2954x; 1.2954x over previous
#include <cuda_runtime.h>
#include <cuda_bf16.h>
#include <math.h>

// ---------------- Problem constants ----------------
#define V_SZ 50257
#define E_SZ 768
#define H_SZ 12
#define L_SZ 6
#define T_SZ 1024
#define B_SZ 2
#define D_SZ 64
#define BT   (B_SZ * T_SZ)      // 2048
#define FF   (4 * E_SZ)         // 3072

// ---------------- Scratch (device globals; no allocations allowed) ----------
__device__ float g_x  [BT * E_SZ];
__device__ float g_h  [BT * E_SZ];
__device__ float g_q  [BT * E_SZ];
__device__ float g_k  [BT * E_SZ];
__device__ float g_v  [BT * E_SZ];
__device__ float g_att[BT * E_SZ];
__device__ float g_m1 [BT * FF];

// ---------------- Embedding ----------------
__global__ void embed_kernel(const int* __restrict__ tok,
                             const float* __restrict__ wte,
                             const float* __restrict__ wpe,
                             float* __restrict__ x) {
    int row = blockIdx.x;
    int t   = row % T_SZ;
    int tk  = tok[row];
    int e   = threadIdx.x * 4;
    const float4 a = *(const float4*)(wte + (size_t)tk * E_SZ + e);
    const float4 b = *(const float4*)(wpe + (size_t)t  * E_SZ + e);
    float4 o;
    o.x = a.x + b.x; o.y = a.y + b.y; o.z = a.z + b.z; o.w = a.w + b.w;
    *(float4*)(x + (size_t)row * E_SZ + e) = o;
}

// ---------------- LayerNorm ----------------
__global__ void layernorm_kernel(const float* __restrict__ x,
                                 const float* __restrict__ sc,
                                 const float* __restrict__ bi,
                                 float* __restrict__ out) {
    int row = blockIdx.x;
    const float* xr = x + (size_t)row * E_SZ;
    float lv[3];
    float s = 0.f, sq = 0.f;
#pragma unroll
    for (int i = 0; i < 3; i++) {
        float t = xr[threadIdx.x + i * 256];
        lv[i] = t; s += t; sq += t * t;
    }
#pragma unroll
    for (int o = 16; o > 0; o >>= 1) {
        s  += __shfl_down_sync(0xffffffffu, s,  o);
        sq += __shfl_down_sync(0xffffffffu, sq, o);
    }
    __shared__ float sa[8], sb[8];
    int w = threadIdx.x >> 5, lane = threadIdx.x & 31;
    if (lane == 0) { sa[w] = s; sb[w] = sq; }
    __syncthreads();
    __shared__ float s_mu, s_rstd;
    if (threadIdx.x == 0) {
        float ts = 0.f, tq = 0.f;
#pragma unroll
        for (int i = 0; i < 8; i++) { ts += sa[i]; tq += sb[i]; }
        float mu  = ts * (1.0f / E_SZ);
        float var = tq * (1.0f / E_SZ) - mu * mu;
        s_mu = mu;
        s_rstd = rsqrtf(var + 1e-5f);
    }
    __syncthreads();
    float mu = s_mu, rstd = s_rstd;
#pragma unroll
    for (int i = 0; i < 3; i++) {
        int c = threadIdx.x + i * 256;
        out[(size_t)row * E_SZ + c] = (lv[i] - mu) * rstd * sc[c] + bi[c];
    }
}

// ---------------- SGEMM: 128xBN tiles, BK=16, double-buffered ----------------
// EPI bit0: +bias[col]; bit1: GELU exact; bit2: +resid[r,c]
__device__ __forceinline__ float gelu_exact(float v) {
    return 0.5f * v * (1.0f + erff(v * 0.70710678118654752f));
}

template <int BN, bool TRANSB, int EPI>
__device__ __forceinline__
void sgemm_dev(const float* __restrict__ A, const float* __restrict__ Bm,
               const float* __restrict__ bias, const float* __restrict__ resid,
               float* __restrict__ C, int N, int K, int bm, int bn) {
    constexpr int BM = 128, BK = 16;
    constexpr int TN = BN / 16;          // 8 (BN=128) or 4 (BN=64)
    __shared__ float As[2][BK][BM];
    __shared__ float Bs[2][BK][BN];

    const int tid = threadIdx.x;
    const int tx  = tid & 15, ty = tid >> 4;

    float acc[8][TN];
#pragma unroll
    for (int i = 0; i < 8; i++)
#pragma unroll
        for (int j = 0; j < TN; j++) acc[i][j] = 0.f;

    // A staging: 2 float4 / thread. f4 id -> row = id>>2, col = (id&3)*4
    const int aRow = tid >> 2;           // 0..63 (+64 for second)
    const int aCol = (tid & 3) * 4;

    // B staging indices
    int bRow = 0, bCol = 0;
    if (TRANSB)            { bRow = tid >> 2; bCol = (tid & 3) * 4; }   // n-row, k-col; 2 f4
    else if (BN == 128)    { bRow = tid >> 5; bCol = (tid & 31) * 4; }  // k-row (+8);  2 f4
    else /* BN == 64 */    { bRow = tid >> 4; bCol = (tid & 15) * 4; }  // k-row;       1 f4

    const int ntiles = K / BK;
    float4 ra0, ra1, rb0, rb1;

    // ---- prologue: load tile 0 ----
    {
        const float* ap = A + (size_t)(bm + aRow) * K + aCol;
        ra0 = *(const float4*)ap;
        ra1 = *(const float4*)(ap + (size_t)64 * K);
        if (TRANSB) {
            int gn0 = bn + bRow, gn1 = bn + bRow + 64;
            rb0 = (gn0 < N) ? *(const float4*)(Bm + (size_t)gn0 * K + bCol)
                            : make_float4(0.f,0.f,0.f,0.f);
            rb1 = (gn1 < N) ? *(const float4*)(Bm + (size_t)gn1 * K + bCol)
                            : make_float4(0.f,0.f,0.f,0.f);
        } else if (BN == 128) {
            const float* bp = Bm + (size_t)bRow * N + bn + bCol;
            rb0 = *(const float4*)bp;
            rb1 = *(const float4*)(bp + (size_t)8 * N);
        } else {
            rb0 = *(const float4*)(Bm + (size_t)bRow * N + bn + bCol);
        }
        As[0][aCol+0][aRow] = ra0.x; As[0][aCol+1][aRow] = ra0.y;
        As[0][aCol+2][aRow] = ra0.z; As[0][aCol+3][aRow] = ra0.w;
        As[0][aCol+0][aRow+64] = ra1.x; As[0][aCol+1][aRow+64] = ra1.y;
        As[0][aCol+2][aRow+64] = ra1.z; As[0][aCol+3][aRow+64] = ra1.w;
        if (TRANSB) {
            Bs[0][bCol+0][bRow] = rb0.x; Bs[0][bCol+1][bRow] = rb0.y;
            Bs[0][bCol+2][bRow] = rb0.z; Bs[0][bCol+3][bRow] = rb0.w;
            Bs[0][bCol+0][bRow+64] = rb1.x; Bs[0][bCol+1][bRow+64] = rb1.y;
            Bs[0][bCol+2][bRow+64] = rb1.z; Bs[0][bCol+3][bRow+64] = rb1.w;
        } else if (BN == 128) {
            *(float4*)&Bs[0][bRow  ][bCol] = rb0;
            *(float4*)&Bs[0][bRow+8][bCol] = rb1;
        } else {
            *(float4*)&Bs[0][bRow][bCol] = rb0;
        }
    }
    __syncthreads();

    for (int kt = 0; kt < ntiles; kt++) {
        const int cur  = kt & 1;
        const bool more = (kt + 1 < ntiles);
        if (more) {
            const int k0 = (kt + 1) * BK;
            const float* ap = A + (size_t)(bm + aRow) * K + k0 + aCol;
            ra0 = *(const float4*)ap;
            ra1 = *(const float4*)(ap + (size_t)64 * K);
            if (TRANSB) {
                int gn0 = bn + bRow, gn1 = bn + bRow + 64;
                rb0 = (gn0 < N) ? *(const float4*)(Bm + (size_t)gn0 * K + k0 + bCol)
                                : make_float4(0.f,0.f,0.f,0.f);
                rb1 = (gn1 < N) ? *(const float4*)(Bm + (size_t)gn1 * K + k0 + bCol)
                                : make_float4(0.f,0.f,0.f,0.f);
            } else if (BN == 128) {
                const float* bp = Bm + (size_t)(k0 + bRow) * N + bn + bCol;
                rb0 = *(const float4*)bp;
                rb1 = *(const float4*)(bp + (size_t)8 * N);
            } else {
                rb0 = *(const float4*)(Bm + (size_t)(k0 + bRow) * N + bn + bCol);
            }
        }
        // ---- compute on stage `cur` ----
#pragma unroll
        for (int kk = 0; kk < BK; kk++) {
            float a[8], b[TN];
#pragma unroll
            for (int i = 0; i < 4; i++) {
                a[i]     = As[cur][kk][ty * 4 + i];
                a[4 + i] = As[cur][kk][64 + ty * 4 + i];
            }
#pragma unroll
            for (int j = 0; j < 4; j++) b[j] = Bs[cur][kk][tx * 4 + j];
            if (BN == 128) {
#pragma unroll
                for (int j = 0; j < 4; j++) b[4 + j] = Bs[cur][kk][64 + tx * 4 + j];
            }
#pragma unroll
            for (int i = 0; i < 8; i++)
#pragma unroll
                for (int j = 0; j < TN; j++) acc[i][j] += a[i] * b[j];
        }
        if (more) {
            const int nxt = cur ^ 1;
            As[nxt][aCol+0][aRow] = ra0.x; As[nxt][aCol+1][aRow] = ra0.y;
            As[nxt][aCol+2][aRow] = ra0.z; As[nxt][aCol+3][aRow] = ra0.w;
            As[nxt][aCol+0][aRow+64] = ra1.x; As[nxt][aCol+1][aRow+64] = ra1.y;
            As[nxt][aCol+2][aRow+64] = ra1.z; As[nxt][aCol+3][aRow+64] = ra1.w;
            if (TRANSB) {
                Bs[nxt][bCol+0][bRow] = rb0.x; Bs[nxt][bCol+1][bRow] = rb0.y;
                Bs[nxt][bCol+2][bRow] = rb0.z; Bs[nxt][bCol+3][bRow] = rb0.w;
                Bs[nxt][bCol+0][bRow+64] = rb1.x; Bs[nxt][bCol+1][bRow+64] = rb1.y;
                Bs[nxt][bCol+2][bRow+64] = rb1.z; Bs[nxt][bCol+3][bRow+64] = rb1.w;
            } else if (BN == 128) {
                *(float4*)&Bs[nxt][bRow  ][bCol] = rb0;
                *(float4*)&Bs[nxt][bRow+8][bCol] = rb1;
            } else {
                *(float4*)&Bs[nxt][bRow][bCol] = rb0;
            }
        }
        __syncthreads();
    }

    // ---- epilogue ----
    constexpr int NG = (BN == 128) ? 2 : 1;
#pragma unroll
    for (int g = 0; g < NG; g++) {
        const int c = bn + g * 64 + tx * 4;
        float4 bv = make_float4(0.f,0.f,0.f,0.f);
        if (EPI & 1) bv = *(const float4*)(bias + c);
#pragma unroll
        for (int i = 0; i < 8; i++) {
            const int r = bm + ((i < 4) ? (ty * 4 + i) : (64 + ty * 4 + (i - 4)));
            float4 v;
            v.x = acc[i][g * 4 + 0]; v.y = acc[i][g * 4 + 1];
            v.z = acc[i][g * 4 + 2]; v.w = acc[i][g * 4 + 3];
            if (EPI & 1) { v.x += bv.x; v.y += bv.y; v.z += bv.z; v.w += bv.w; }
            if (EPI & 2) {
                v.x = gelu_exact(v.x); v.y = gelu_exact(v.y);
                v.z = gelu_exact(v.z); v.w = gelu_exact(v.w);
            }
            if (EPI & 4) {
                float4 rr = *(const float4*)(resid + (size_t)r * N + c);
                v.x += rr.x; v.y += rr.y; v.z += rr.z; v.w += rr.w;
            }
            if (!TRANSB) {
                // N is a multiple of 4 and rows are 16B-aligned here
                *(float4*)(C + (size_t)r * N + c) = v;
            } else {
                // N may be odd (V=50257): row stride breaks 16B alignment.
                // Scalar stores, bounds-checked.
                float vv[4] = {v.x, v.y, v.z, v.w};
                float* cp = C + (size_t)r * N;
#pragma unroll
                for (int jj = 0; jj < 4; jj++)
                    if (c + jj < N) cp[c + jj] = vv[jj];
            }
        }
    }
}

template <int BN, bool TRANSB, int EPI>
__global__ __launch_bounds__(256, 2)
void sgemm_k(const float* __restrict__ A, const float* __restrict__ Bm,
             const float* __restrict__ bias, const float* __restrict__ resid,
             float* __restrict__ C, int N, int K) {
    sgemm_dev<BN, TRANSB, EPI>(A, Bm, bias, resid, C, N, K,
                               blockIdx.y * 128, blockIdx.x * BN);
}

// QKV batched via blockIdx.z
__global__ __launch_bounds__(256, 2)
void qkv_k(const float* __restrict__ A,
           const float* __restrict__ Wq, const float* __restrict__ Wk,
           const float* __restrict__ Wv,
           float* __restrict__ q, float* __restrict__ k, float* __restrict__ v) {
    const float* Bm = (blockIdx.z == 0) ? Wq : (blockIdx.z == 1) ? Wk : Wv;
    float* C        = (blockIdx.z == 0) ? q  : (blockIdx.z == 1) ? k  : v;
    sgemm_dev<64, false, 0>(A, Bm, nullptr, nullptr, C, E_SZ, E_SZ,
                            blockIdx.y * 128, blockIdx.x * 64);
}

// ---------------- Causal attention, online softmax ----------------
__global__ __launch_bounds__(128)
void attn_kernel(const float* __restrict__ q, const float* __restrict__ k,
                 const float* __restrict__ v, float* __restrict__ o) {
    const int bh = blockIdx.y;
    const int b  = bh / H_SZ, h = bh % H_SZ;
    const int qi = blockIdx.x * 128 + threadIdx.x;

    float qr[D_SZ];
    {
        const float* qp = q + ((size_t)(b * T_SZ + qi) * E_SZ) + h * D_SZ;
#pragma unroll
        for (int d = 0; d < D_SZ; d++) qr[d] = qp[d] * 0.125f;
    }
    float m = -1e30f, l = 0.f;
    float accv[D_SZ];
#pragma unroll
    for (int d = 0; d < D_SZ; d++) accv[d] = 0.f;

    __shared__ float Ks[64][D_SZ];
    __shared__ float Vs[64][D_SZ];

    const int qmax = blockIdx.x * 128 + 127;
    for (int kt = 0; kt <= qmax; kt += 64) {
        for (int i = threadIdx.x; i < 64 * 16; i += 128) {
            int rr = i >> 4, cc = (i & 15) * 4;
            size_t base = ((size_t)(b * T_SZ + kt + rr) * E_SZ) + h * D_SZ + cc;
            float4 kv = *(const float4*)(k + base);
            Ks[rr][cc] = kv.x; Ks[rr][cc + 1] = kv.y; Ks[rr][cc + 2] = kv.z; Ks[rr][cc + 3] = kv.w;
            float4 vv = *(const float4*)(v + base);
            Vs[rr][cc] = vv.x; Vs[rr][cc + 1] = vv.y; Vs[rr][cc + 2] = vv.z; Vs[rr][cc + 3] = vv.w;
        }
        __syncthreads();
        int kend = qi - kt + 1;
        if (kend > 64) kend = 64;
        for (int kk = 0; kk < kend; kk++) {
            float s = 0.f;
#pragma unroll
            for (int d = 0; d < D_SZ; d++) s += qr[d] * Ks[kk][d];
            float mn = fmaxf(m, s);
            float c  = __expf(m - mn);
            float p  = __expf(s - mn);
            l = l * c + p;
#pragma unroll
            for (int d = 0; d < D_SZ; d++) accv[d] = accv[d] * c + p * Vs[kk][d];
            m = mn;
        }
        __syncthreads();
    }
    float inv = 1.f / l;
    float* op = o + ((size_t)(b * T_SZ + qi) * E_SZ) + h * D_SZ;
#pragma unroll
    for (int d = 0; d < D_SZ; d++) op[d] = accv[d] * inv;
}

// ---------------- Host orchestration ----------------
extern "C" void kernel_launch(void* const* d_in, const int* in_sizes, int n_in,
                              void* d_out, int out_size) {
    (void)in_sizes; (void)n_in; (void)out_size;
    const int*   tokens = (const int*)  d_in[0];
    const float* wte    = (const float*)d_in[1];
    const float* wpe    = (const float*)d_in[2];
    const float* Wq     = (const float*)d_in[3];
    const float* Wk     = (const float*)d_in[4];
    const float* Wv     = (const float*)d_in[5];
    const float* Wo     = (const float*)d_in[6];
    const float* bo     = (const float*)d_in[7];
    const float* ln1_s  = (const float*)d_in[8];
    const float* ln1_b  = (const float*)d_in[9];
    const float* W1     = (const float*)d_in[10];
    const float* b1     = (const float*)d_in[11];
    const float* W2     = (const float*)d_in[12];
    const float* b2     = (const float*)d_in[13];
    const float* ln2_s  = (const float*)d_in[14];
    const float* ln2_b  = (const float*)d_in[15];
    const float* lnf_s  = (const float*)d_in[16];
    const float* lnf_b  = (const float*)d_in[17];
    float* out = (float*)d_out;

    float *x, *h, *q, *k, *v, *att, *m1;
    cudaGetSymbolAddress((void**)&x,   g_x);
    cudaGetSymbolAddress((void**)&h,   g_h);
    cudaGetSymbolAddress((void**)&q,   g_q);
    cudaGetSymbolAddress((void**)&k,   g_k);
    cudaGetSymbolAddress((void**)&v,   g_v);
    cudaGetSymbolAddress((void**)&att, g_att);
    cudaGetSymbolAddress((void**)&m1,  g_m1);

    embed_kernel<<<BT, 192>>>(tokens, wte, wpe, x);

    const dim3 gE64(E_SZ / 64, BT / 128);        // 12 x 16
    const dim3 gQKV(E_SZ / 64, BT / 128, 3);     // 12 x 16 x 3
    const dim3 gF128(FF / 128, BT / 128);        // 24 x 16

    for (int l = 0; l < L_SZ; l++) {
        const size_t wOff  = (size_t)l * E_SZ * E_SZ;
        const size_t w1Off = (size_t)l * E_SZ * FF;
        const size_t vOff  = (size_t)l * E_SZ;
        const size_t fOff  = (size_t)l * FF;

        layernorm_kernel<<<BT, 256>>>(x, ln1_s + vOff, ln1_b + vOff, h);
        qkv_k<<<gQKV, 256>>>(h, Wq + wOff, Wk + wOff, Wv + wOff, q, k, v);
        attn_kernel<<<dim3(T_SZ / 128, B_SZ * H_SZ), 128>>>(q, k, v, att);
        sgemm_k<64, false, 5><<<gE64, 256>>>(att, Wo + wOff, bo + vOff, x, x, E_SZ, E_SZ);
        layernorm_kernel<<<BT, 256>>>(x, ln2_s + vOff, ln2_b + vOff, h);
        sgemm_k<128, false, 3><<<gF128, 256>>>(h, W1 + w1Off, b1 + fOff, nullptr, m1, FF, E_SZ);
        sgemm_k<64, false, 5><<<gE64, 256>>>(m1, W2 + w1Off, b2 + vOff, x, x, E_SZ, FF);
    }

    layernorm_kernel<<<BT, 256>>>(x, lnf_s, lnf_b, h);
    sgemm_k<128, true, 0><<<dim3((V_SZ + 127) / 128, BT / 128), 256>>>(
        h, wte, nullptr, nullptr, out, V_SZ, E_SZ);
}

// round 4
// speedup vs baseline: 1.3361x; 1.0314x over previous
#include <cuda_runtime.h>
#include <cuda_bf16.h>
#include <math.h>

// ---------------- Problem constants ----------------
#define V_SZ 50257
#define E_SZ 768
#define H_SZ 12
#define L_SZ 6
#define T_SZ 1024
#define B_SZ 2
#define D_SZ 64
#define BT   (B_SZ * T_SZ)      // 2048
#define FF   (4 * E_SZ)         // 3072

// ---------------- Scratch (device globals; no allocations allowed) ----------
__device__ float g_x  [BT * E_SZ];
__device__ float g_h  [BT * E_SZ];
__device__ float g_q  [BT * E_SZ];
__device__ float g_k  [BT * E_SZ];
__device__ float g_v  [BT * E_SZ];
__device__ float g_att[BT * E_SZ];
__device__ float g_m1 [BT * FF];

// ---------------- Embedding ----------------
__global__ void embed_kernel(const int* __restrict__ tok,
                             const float* __restrict__ wte,
                             const float* __restrict__ wpe,
                             float* __restrict__ x) {
    int row = blockIdx.x;
    int t   = row % T_SZ;
    int tk  = tok[row];
    int e   = threadIdx.x * 4;
    const float4 a = *(const float4*)(wte + (size_t)tk * E_SZ + e);
    const float4 b = *(const float4*)(wpe + (size_t)t  * E_SZ + e);
    float4 o;
    o.x = a.x + b.x; o.y = a.y + b.y; o.z = a.z + b.z; o.w = a.w + b.w;
    *(float4*)(x + (size_t)row * E_SZ + e) = o;
}

// ---------------- LayerNorm ----------------
__global__ void layernorm_kernel(const float* __restrict__ x,
                                 const float* __restrict__ sc,
                                 const float* __restrict__ bi,
                                 float* __restrict__ out) {
    int row = blockIdx.x;
    const float* xr = x + (size_t)row * E_SZ;
    float lv[3];
    float s = 0.f, sq = 0.f;
#pragma unroll
    for (int i = 0; i < 3; i++) {
        float t = xr[threadIdx.x + i * 256];
        lv[i] = t; s += t; sq += t * t;
    }
#pragma unroll
    for (int o = 16; o > 0; o >>= 1) {
        s  += __shfl_down_sync(0xffffffffu, s,  o);
        sq += __shfl_down_sync(0xffffffffu, sq, o);
    }
    __shared__ float sa[8], sb[8];
    int w = threadIdx.x >> 5, lane = threadIdx.x & 31;
    if (lane == 0) { sa[w] = s; sb[w] = sq; }
    __syncthreads();
    __shared__ float s_mu, s_rstd;
    if (threadIdx.x == 0) {
        float ts = 0.f, tq = 0.f;
#pragma unroll
        for (int i = 0; i < 8; i++) { ts += sa[i]; tq += sb[i]; }
        float mu  = ts * (1.0f / E_SZ);
        float var = tq * (1.0f / E_SZ) - mu * mu;
        s_mu = mu;
        s_rstd = rsqrtf(var + 1e-5f);
    }
    __syncthreads();
    float mu = s_mu, rstd = s_rstd;
#pragma unroll
    for (int i = 0; i < 3; i++) {
        int c = threadIdx.x + i * 256;
        out[(size_t)row * E_SZ + c] = (lv[i] - mu) * rstd * sc[c] + bi[c];
    }
}

// ---------------- SGEMM: 128xBN tiles, BK=16, double-buffered ----------------
__device__ __forceinline__ float gelu_exact(float v) {
    return 0.5f * v * (1.0f + erff(v * 0.70710678118654752f));
}

template <int BN, bool TRANSB, int EPI>
__device__ __forceinline__
void sgemm_dev(const float* __restrict__ A, const float* __restrict__ Bm,
               const float* __restrict__ bias, const float* __restrict__ resid,
               float* __restrict__ C, int N, int K, int bm, int bn) {
    constexpr int BM = 128, BK = 16;
    constexpr int TN = BN / 16;
    __shared__ float As[2][BK][BM];
    __shared__ float Bs[2][BK][BN];

    const int tid = threadIdx.x;
    const int tx  = tid & 15, ty = tid >> 4;

    float acc[8][TN];
#pragma unroll
    for (int i = 0; i < 8; i++)
#pragma unroll
        for (int j = 0; j < TN; j++) acc[i][j] = 0.f;

    const int aRow = tid >> 2;
    const int aCol = (tid & 3) * 4;

    int bRow = 0, bCol = 0;
    if (TRANSB)            { bRow = tid >> 2; bCol = (tid & 3) * 4; }
    else if (BN == 128)    { bRow = tid >> 5; bCol = (tid & 31) * 4; }
    else                   { bRow = tid >> 4; bCol = (tid & 15) * 4; }

    const int ntiles = K / BK;
    float4 ra0, ra1, rb0, rb1;

    {
        const float* ap = A + (size_t)(bm + aRow) * K + aCol;
        ra0 = *(const float4*)ap;
        ra1 = *(const float4*)(ap + (size_t)64 * K);
        if (TRANSB) {
            int gn0 = bn + bRow, gn1 = bn + bRow + 64;
            rb0 = (gn0 < N) ? *(const float4*)(Bm + (size_t)gn0 * K + bCol)
                            : make_float4(0.f,0.f,0.f,0.f);
            rb1 = (gn1 < N) ? *(const float4*)(Bm + (size_t)gn1 * K + bCol)
                            : make_float4(0.f,0.f,0.f,0.f);
        } else if (BN == 128) {
            const float* bp = Bm + (size_t)bRow * N + bn + bCol;
            rb0 = *(const float4*)bp;
            rb1 = *(const float4*)(bp + (size_t)8 * N);
        } else {
            rb0 = *(const float4*)(Bm + (size_t)bRow * N + bn + bCol);
        }
        As[0][aCol+0][aRow] = ra0.x; As[0][aCol+1][aRow] = ra0.y;
        As[0][aCol+2][aRow] = ra0.z; As[0][aCol+3][aRow] = ra0.w;
        As[0][aCol+0][aRow+64] = ra1.x; As[0][aCol+1][aRow+64] = ra1.y;
        As[0][aCol+2][aRow+64] = ra1.z; As[0][aCol+3][aRow+64] = ra1.w;
        if (TRANSB) {
            Bs[0][bCol+0][bRow] = rb0.x; Bs[0][bCol+1][bRow] = rb0.y;
            Bs[0][bCol+2][bRow] = rb0.z; Bs[0][bCol+3][bRow] = rb0.w;
            Bs[0][bCol+0][bRow+64] = rb1.x; Bs[0][bCol+1][bRow+64] = rb1.y;
            Bs[0][bCol+2][bRow+64] = rb1.z; Bs[0][bCol+3][bRow+64] = rb1.w;
        } else if (BN == 128) {
            *(float4*)&Bs[0][bRow  ][bCol] = rb0;
            *(float4*)&Bs[0][bRow+8][bCol] = rb1;
        } else {
            *(float4*)&Bs[0][bRow][bCol] = rb0;
        }
    }
    __syncthreads();

    for (int kt = 0; kt < ntiles; kt++) {
        const int cur  = kt & 1;
        const bool more = (kt + 1 < ntiles);
        if (more) {
            const int k0 = (kt + 1) * BK;
            const float* ap = A + (size_t)(bm + aRow) * K + k0 + aCol;
            ra0 = *(const float4*)ap;
            ra1 = *(const float4*)(ap + (size_t)64 * K);
            if (TRANSB) {
                int gn0 = bn + bRow, gn1 = bn + bRow + 64;
                rb0 = (gn0 < N) ? *(const float4*)(Bm + (size_t)gn0 * K + k0 + bCol)
                                : make_float4(0.f,0.f,0.f,0.f);
                rb1 = (gn1 < N) ? *(const float4*)(Bm + (size_t)gn1 * K + k0 + bCol)
                                : make_float4(0.f,0.f,0.f,0.f);
            } else if (BN == 128) {
                const float* bp = Bm + (size_t)(k0 + bRow) * N + bn + bCol;
                rb0 = *(const float4*)bp;
                rb1 = *(const float4*)(bp + (size_t)8 * N);
            } else {
                rb0 = *(const float4*)(Bm + (size_t)(k0 + bRow) * N + bn + bCol);
            }
        }
#pragma unroll
        for (int kk = 0; kk < BK; kk++) {
            float a[8], b[TN];
#pragma unroll
            for (int i = 0; i < 4; i++) {
                a[i]     = As[cur][kk][ty * 4 + i];
                a[4 + i] = As[cur][kk][64 + ty * 4 + i];
            }
#pragma unroll
            for (int j = 0; j < 4; j++) b[j] = Bs[cur][kk][tx * 4 + j];
            if (BN == 128) {
#pragma unroll
                for (int j = 0; j < 4; j++) b[4 + j] = Bs[cur][kk][64 + tx * 4 + j];
            }
#pragma unroll
            for (int i = 0; i < 8; i++)
#pragma unroll
                for (int j = 0; j < TN; j++) acc[i][j] += a[i] * b[j];
        }
        if (more) {
            const int nxt = cur ^ 1;
            As[nxt][aCol+0][aRow] = ra0.x; As[nxt][aCol+1][aRow] = ra0.y;
            As[nxt][aCol+2][aRow] = ra0.z; As[nxt][aCol+3][aRow] = ra0.w;
            As[nxt][aCol+0][aRow+64] = ra1.x; As[nxt][aCol+1][aRow+64] = ra1.y;
            As[nxt][aCol+2][aRow+64] = ra1.z; As[nxt][aCol+3][aRow+64] = ra1.w;
            if (TRANSB) {
                Bs[nxt][bCol+0][bRow] = rb0.x; Bs[nxt][bCol+1][bRow] = rb0.y;
                Bs[nxt][bCol+2][bRow] = rb0.z; Bs[nxt][bCol+3][bRow] = rb0.w;
                Bs[nxt][bCol+0][bRow+64] = rb1.x; Bs[nxt][bCol+1][bRow+64] = rb1.y;
                Bs[nxt][bCol+2][bRow+64] = rb1.z; Bs[nxt][bCol+3][bRow+64] = rb1.w;
            } else if (BN == 128) {
                *(float4*)&Bs[nxt][bRow  ][bCol] = rb0;
                *(float4*)&Bs[nxt][bRow+8][bCol] = rb1;
            } else {
                *(float4*)&Bs[nxt][bRow][bCol] = rb0;
            }
        }
        __syncthreads();
    }

    constexpr int NG = (BN == 128) ? 2 : 1;
#pragma unroll
    for (int g = 0; g < NG; g++) {
        const int c = bn + g * 64 + tx * 4;
        float4 bv = make_float4(0.f,0.f,0.f,0.f);
        if (EPI & 1) bv = *(const float4*)(bias + c);
#pragma unroll
        for (int i = 0; i < 8; i++) {
            const int r = bm + ((i < 4) ? (ty * 4 + i) : (64 + ty * 4 + (i - 4)));
            float4 v;
            v.x = acc[i][g * 4 + 0]; v.y = acc[i][g * 4 + 1];
            v.z = acc[i][g * 4 + 2]; v.w = acc[i][g * 4 + 3];
            if (EPI & 1) { v.x += bv.x; v.y += bv.y; v.z += bv.z; v.w += bv.w; }
            if (EPI & 2) {
                v.x = gelu_exact(v.x); v.y = gelu_exact(v.y);
                v.z = gelu_exact(v.z); v.w = gelu_exact(v.w);
            }
            if (EPI & 4) {
                float4 rr = *(const float4*)(resid + (size_t)r * N + c);
                v.x += rr.x; v.y += rr.y; v.z += rr.z; v.w += rr.w;
            }
            if (!TRANSB) {
                *(float4*)(C + (size_t)r * N + c) = v;
            } else {
                // N may be odd (V=50257): scalar bounds-checked stores
                float vv[4] = {v.x, v.y, v.z, v.w};
                float* cp = C + (size_t)r * N;
#pragma unroll
                for (int jj = 0; jj < 4; jj++)
                    if (c + jj < N) cp[c + jj] = vv[jj];
            }
        }
    }
}

template <int BN, bool TRANSB, int EPI>
__global__ __launch_bounds__(256, 2)
void sgemm_k(const float* __restrict__ A, const float* __restrict__ Bm,
             const float* __restrict__ bias, const float* __restrict__ resid,
             float* __restrict__ C, int N, int K) {
    sgemm_dev<BN, TRANSB, EPI>(A, Bm, bias, resid, C, N, K,
                               blockIdx.y * 128, blockIdx.x * BN);
}

__global__ __launch_bounds__(256, 2)
void qkv_k(const float* __restrict__ A,
           const float* __restrict__ Wq, const float* __restrict__ Wk,
           const float* __restrict__ Wv,
           float* __restrict__ q, float* __restrict__ k, float* __restrict__ v) {
    const float* Bm = (blockIdx.z == 0) ? Wq : (blockIdx.z == 1) ? Wk : Wv;
    float* C        = (blockIdx.z == 0) ? q  : (blockIdx.z == 1) ? k  : v;
    sgemm_dev<64, false, 0>(A, Bm, nullptr, nullptr, C, E_SZ, E_SZ,
                            blockIdx.y * 128, blockIdx.x * 64);
}

// ---------------- Causal attention v2: pair-split + chunked softmax --------
// 2 threads per query (each owns 32 of 64 dims). 64 queries/block (128 thr).
// Chunked (16-key) online softmax: one rescale per 16 keys, not per key.
__global__ __launch_bounds__(128, 4)
void attn_kernel(const float* __restrict__ q, const float* __restrict__ k,
                 const float* __restrict__ v, float* __restrict__ o) {
    const int bh   = blockIdx.y;
    const int b    = bh / H_SZ, h = bh % H_SZ;
    const int ql   = threadIdx.x >> 1;        // 0..63
    const int half = threadIdx.x & 1;         // which 32-dim half
    const int qi   = blockIdx.x * 64 + ql;
    const int hoff = h * D_SZ + half * 32;

    float qr[32];
    {
        const float* qp = q + ((size_t)(b * T_SZ + qi) * E_SZ) + hoff;
#pragma unroll
        for (int d = 0; d < 32; d += 4) {
            float4 t = *(const float4*)(qp + d);
            qr[d+0] = t.x * 0.125f; qr[d+1] = t.y * 0.125f;
            qr[d+2] = t.z * 0.125f; qr[d+3] = t.w * 0.125f;
        }
    }
    float m = -1e30f, l = 0.f;
    float accv[32];
#pragma unroll
    for (int d = 0; d < 32; d++) accv[d] = 0.f;

    // stride 68 (=4 mod 32 banks) -> conflict-free float4 stores, rows 16B-aligned
    __shared__ float Ks[64][68];
    __shared__ float Vs[64][68];

    const int qmax = blockIdx.x * 64 + 63;
    for (int kt = 0; kt <= qmax; kt += 64) {
        // cooperative tile load: 1024 float4 per tensor, 8 per thread, coalesced
#pragma unroll
        for (int i = 0; i < 8; i++) {
            int f   = threadIdx.x + i * 128;   // float4 id
            int rr  = f >> 4;
            int cc  = (f & 15) * 4;
            size_t gb = ((size_t)(b * T_SZ + kt + rr) * E_SZ) + h * D_SZ + cc;
            *(float4*)&Ks[rr][cc] = *(const float4*)(k + gb);
            *(float4*)&Vs[rr][cc] = *(const float4*)(v + gb);
        }
        __syncthreads();

        const int kend = min(qi - kt + 1, 64);   // >= 1 always for this block
        for (int c0 = 0; c0 < 64; c0 += 16) {
            if (c0 >= kend) break;
            float s[16];
#pragma unroll
            for (int j = 0; j < 16; j++) {
                float a0 = 0.f, a1 = 0.f;
#pragma unroll
                for (int d = 0; d < 32; d += 8) {
                    float4 k0 = *(const float4*)&Ks[c0 + j][half * 32 + d];
                    float4 k1 = *(const float4*)&Ks[c0 + j][half * 32 + d + 4];
                    a0 += qr[d+0]*k0.x + qr[d+1]*k0.y + qr[d+2]*k0.z + qr[d+3]*k0.w;
                    a1 += qr[d+4]*k1.x + qr[d+5]*k1.y + qr[d+6]*k1.z + qr[d+7]*k1.w;
                }
                s[j] = a0 + a1;
            }
#pragma unroll
            for (int j = 0; j < 16; j++) {
                s[j] += __shfl_xor_sync(0xffffffffu, s[j], 1);
                if (c0 + j >= kend) s[j] = -1e30f;
            }
            float cm = s[0];
#pragma unroll
            for (int j = 1; j < 16; j++) cm = fmaxf(cm, s[j]);
            float mn = fmaxf(m, cm);
            float cf = __expf(m - mn);
            m = mn;
#pragma unroll
            for (int d = 0; d < 32; d++) accv[d] *= cf;
            float ps = 0.f;
#pragma unroll
            for (int j = 0; j < 16; j++) {
                float p = __expf(s[j] - mn);
                ps += p;
#pragma unroll
                for (int d = 0; d < 32; d += 4) {
                    float4 vv = *(const float4*)&Vs[c0 + j][half * 32 + d];
                    accv[d+0] += p * vv.x; accv[d+1] += p * vv.y;
                    accv[d+2] += p * vv.z; accv[d+3] += p * vv.w;
                }
            }
            l = l * cf + ps;
        }
        __syncthreads();
    }
    const float inv = 1.f / l;
    float* op = o + ((size_t)(b * T_SZ + qi) * E_SZ) + hoff;
#pragma unroll
    for (int d = 0; d < 32; d += 4) {
        float4 t;
        t.x = accv[d+0] * inv; t.y = accv[d+1] * inv;
        t.z = accv[d+2] * inv; t.w = accv[d+3] * inv;
        *(float4*)(op + d) = t;
    }
}

// ---------------- Host orchestration ----------------
extern "C" void kernel_launch(void* const* d_in, const int* in_sizes, int n_in,
                              void* d_out, int out_size) {
    (void)in_sizes; (void)n_in; (void)out_size;
    const int*   tokens = (const int*)  d_in[0];
    const float* wte    = (const float*)d_in[1];
    const float* wpe    = (const float*)d_in[2];
    const float* Wq     = (const float*)d_in[3];
    const float* Wk     = (const float*)d_in[4];
    const float* Wv     = (const float*)d_in[5];
    const float* Wo     = (const float*)d_in[6];
    const float* bo     = (const float*)d_in[7];
    const float* ln1_s  = (const float*)d_in[8];
    const float* ln1_b  = (const float*)d_in[9];
    const float* W1     = (const float*)d_in[10];
    const float* b1     = (const float*)d_in[11];
    const float* W2     = (const float*)d_in[12];
    const float* b2     = (const float*)d_in[13];
    const float* ln2_s  = (const float*)d_in[14];
    const float* ln2_b  = (const float*)d_in[15];
    const float* lnf_s  = (const float*)d_in[16];
    const float* lnf_b  = (const float*)d_in[17];
    float* out = (float*)d_out;

    float *x, *h, *q, *k, *v, *att, *m1;
    cudaGetSymbolAddress((void**)&x,   g_x);
    cudaGetSymbolAddress((void**)&h,   g_h);
    cudaGetSymbolAddress((void**)&q,   g_q);
    cudaGetSymbolAddress((void**)&k,   g_k);
    cudaGetSymbolAddress((void**)&v,   g_v);
    cudaGetSymbolAddress((void**)&att, g_att);
    cudaGetSymbolAddress((void**)&m1,  g_m1);

    embed_kernel<<<BT, 192>>>(tokens, wte, wpe, x);

    const dim3 gE64(E_SZ / 64, BT / 128);        // 12 x 16
    const dim3 gQKV(E_SZ / 64, BT / 128, 3);     // 12 x 16 x 3
    const dim3 gF128(FF / 128, BT / 128);        // 24 x 16
    const dim3 gATT(T_SZ / 64, B_SZ * H_SZ);     // 16 x 24 = 384 blocks

    for (int l = 0; l < L_SZ; l++) {
        const size_t wOff  = (size_t)l * E_SZ * E_SZ;
        const size_t w1Off = (size_t)l * E_SZ * FF;
        const size_t vOff  = (size_t)l * E_SZ;
        const size_t fOff  = (size_t)l * FF;

        layernorm_kernel<<<BT, 256>>>(x, ln1_s + vOff, ln1_b + vOff, h);
        qkv_k<<<gQKV, 256>>>(h, Wq + wOff, Wk + wOff, Wv + wOff, q, k, v);
        attn_kernel<<<gATT, 128>>>(q, k, v, att);
        sgemm_k<64, false, 5><<<gE64, 256>>>(att, Wo + wOff, bo + vOff, x, x, E_SZ, E_SZ);
        layernorm_kernel<<<BT, 256>>>(x, ln2_s + vOff, ln2_b + vOff, h);
        sgemm_k<128, false, 3><<<gF128, 256>>>(h, W1 + w1Off, b1 + fOff, nullptr, m1, FF, E_SZ);
        sgemm_k<64, false, 5><<<gE64, 256>>>(m1, W2 + w1Off, b2 + vOff, x, x, E_SZ, FF);
    }

    layernorm_kernel<<<BT, 256>>>(x, lnf_s, lnf_b, h);
    sgemm_k<128, true, 0><<<dim3((V_SZ + 127) / 128, BT / 128), 256>>>(
        h, wte, nullptr, nullptr, out, V_SZ, E_SZ);
}

// round 5
// speedup vs baseline: 2.2794x; 1.7060x over previous
#include <cuda_runtime.h>
#include <cuda_bf16.h>
#include <math.h>

// ---------------- Problem constants ----------------
#define V_SZ 50257
#define E_SZ 768
#define H_SZ 12
#define L_SZ 6
#define T_SZ 1024
#define B_SZ 2
#define D_SZ 64
#define BT   (B_SZ * T_SZ)      // 2048
#define FF   (4 * E_SZ)         // 3072

// ---------------- Scratch (device globals; no allocations allowed) ----------
__device__ float g_x  [BT * E_SZ];
__device__ float g_h  [BT * E_SZ];
__device__ float g_q  [BT * E_SZ];
__device__ float g_k  [BT * E_SZ];
__device__ float g_v  [BT * E_SZ];
__device__ float g_att[BT * E_SZ];
__device__ float g_m1 [BT * FF];

// ---------------- Embedding ----------------
__global__ void embed_kernel(const int* __restrict__ tok,
                             const float* __restrict__ wte,
                             const float* __restrict__ wpe,
                             float* __restrict__ x) {
    int row = blockIdx.x;
    int t   = row % T_SZ;
    int tk  = tok[row];
    int e   = threadIdx.x * 4;
    const float4 a = *(const float4*)(wte + (size_t)tk * E_SZ + e);
    const float4 b = *(const float4*)(wpe + (size_t)t  * E_SZ + e);
    float4 o;
    o.x = a.x + b.x; o.y = a.y + b.y; o.z = a.z + b.z; o.w = a.w + b.w;
    *(float4*)(x + (size_t)row * E_SZ + e) = o;
}

// ---------------- LayerNorm ----------------
__global__ void layernorm_kernel(const float* __restrict__ x,
                                 const float* __restrict__ sc,
                                 const float* __restrict__ bi,
                                 float* __restrict__ out) {
    int row = blockIdx.x;
    const float* xr = x + (size_t)row * E_SZ;
    float lv[3];
    float s = 0.f, sq = 0.f;
#pragma unroll
    for (int i = 0; i < 3; i++) {
        float t = xr[threadIdx.x + i * 256];
        lv[i] = t; s += t; sq += t * t;
    }
#pragma unroll
    for (int o = 16; o > 0; o >>= 1) {
        s  += __shfl_down_sync(0xffffffffu, s,  o);
        sq += __shfl_down_sync(0xffffffffu, sq, o);
    }
    __shared__ float sa[8], sb[8];
    int w = threadIdx.x >> 5, lane = threadIdx.x & 31;
    if (lane == 0) { sa[w] = s; sb[w] = sq; }
    __syncthreads();
    __shared__ float s_mu, s_rstd;
    if (threadIdx.x == 0) {
        float ts = 0.f, tq = 0.f;
#pragma unroll
        for (int i = 0; i < 8; i++) { ts += sa[i]; tq += sb[i]; }
        float mu  = ts * (1.0f / E_SZ);
        float var = tq * (1.0f / E_SZ) - mu * mu;
        s_mu = mu;
        s_rstd = rsqrtf(var + 1e-5f);
    }
    __syncthreads();
    float mu = s_mu, rstd = s_rstd;
#pragma unroll
    for (int i = 0; i < 3; i++) {
        int c = threadIdx.x + i * 256;
        out[(size_t)row * E_SZ + c] = (lv[i] - mu) * rstd * sc[c] + bi[c];
    }
}

// ---------------- TF32 tensor-core GEMM ----------------
// C[M,N] = A[M,K] @ B (+epilogue).  BM=128, BN=64, BK=16 double-buffered.
// 256 threads = 8 warps (4 m x 2 n), warp tile 32x32 = 2x4 m16n8k8 atoms.
// EPI bit0: +bias[col]; bit1: GELU exact; bit2: +resid[r,c]
__device__ __forceinline__ float gelu_exact(float v) {
    return 0.5f * v * (1.0f + erff(v * 0.70710678118654752f));
}
__device__ __forceinline__ unsigned f2tf(float f) {
    unsigned u;
    asm("cvt.rna.tf32.f32 %0, %1;" : "=r"(u) : "f"(f));
    return u;
}
__device__ __forceinline__ void mma_tf32(float* d, const unsigned* a, const unsigned* b) {
    asm volatile(
        "mma.sync.aligned.m16n8k8.row.col.f32.tf32.tf32.f32 "
        "{%0,%1,%2,%3}, {%4,%5,%6,%7}, {%8,%9}, {%0,%1,%2,%3};"
        : "+f"(d[0]), "+f"(d[1]), "+f"(d[2]), "+f"(d[3])
        : "r"(a[0]), "r"(a[1]), "r"(a[2]), "r"(a[3]), "r"(b[0]), "r"(b[1]));
}

template <bool TRANSB, int EPI>
__device__ __forceinline__
void tgemm_dev(const float* __restrict__ A, const float* __restrict__ Bm,
               const float* __restrict__ bias, const float* __restrict__ resid,
               float* __restrict__ C, int N, int K, int bm, int bn) {
    constexpr int BK = 16;
    // A smem: [m][16+4] stride-20 word pattern -> conflict-free frag loads
    __shared__ unsigned As[2][128][20];
    // B smem: TRANSB -> [n][20] (conflict-free), else [k][68] (2-way on frags)
    __shared__ unsigned Bs[2][TRANSB ? (64 * 20) : (16 * 68)];

    const int tid  = threadIdx.x;
    const int lane = tid & 31;
    const int wid  = tid >> 5;
    const int wm   = (wid & 3) * 32;     // warp m offset in tile
    const int wn   = (wid >> 2) * 32;    // warp n offset
    const int g    = lane >> 2;          // group id 0..7
    const int t    = lane & 3;           // thread-in-group

    float acc[2][4][4];
#pragma unroll
    for (int i = 0; i < 2; i++)
#pragma unroll
        for (int j = 0; j < 4; j++)
#pragma unroll
            for (int r = 0; r < 4; r++) acc[i][j][r] = 0.f;

    // staging indices
    const int ar = tid >> 2;             // A row 0..63 (+64 for second f4)
    const int ak = (tid & 3) * 4;        // A k col
    const int nbK = tid >> 4;            // non-trans B: k row 0..15
    const int nbN = (tid & 15) * 4;      // non-trans B: n col
    const int tbN = tid >> 2;            // trans B: n row 0..63
    const int tbK = (tid & 3) * 4;       // trans B: k col

    const int ntiles = K / BK;
    float4 a0, a1, bb;

    // ---- prologue: tile 0 global loads ----
    {
        const float* ap = A + (size_t)(bm + ar) * K + ak;
        a0 = *(const float4*)ap;
        a1 = *(const float4*)(ap + (size_t)64 * K);
        if (TRANSB) {
            int gn = bn + tbN;
            bb = (gn < N) ? *(const float4*)(Bm + (size_t)gn * K + tbK)
                          : make_float4(0.f, 0.f, 0.f, 0.f);
        } else {
            bb = *(const float4*)(Bm + (size_t)nbK * N + bn + nbN);
        }
        As[0][ar][ak+0] = f2tf(a0.x); As[0][ar][ak+1] = f2tf(a0.y);
        As[0][ar][ak+2] = f2tf(a0.z); As[0][ar][ak+3] = f2tf(a0.w);
        As[0][ar+64][ak+0] = f2tf(a1.x); As[0][ar+64][ak+1] = f2tf(a1.y);
        As[0][ar+64][ak+2] = f2tf(a1.z); As[0][ar+64][ak+3] = f2tf(a1.w);
        if (TRANSB) {
            unsigned* bp = &Bs[0][tbN * 20 + tbK];
            bp[0] = f2tf(bb.x); bp[1] = f2tf(bb.y);
            bp[2] = f2tf(bb.z); bp[3] = f2tf(bb.w);
        } else {
            Bs[0][nbK * 68 + nbN + 0] = f2tf(bb.x);
            Bs[0][nbK * 68 + nbN + 1] = f2tf(bb.y);
            Bs[0][nbK * 68 + nbN + 2] = f2tf(bb.z);
            Bs[0][nbK * 68 + nbN + 3] = f2tf(bb.w);
        }
    }
    __syncthreads();

    for (int kt = 0; kt < ntiles; kt++) {
        const int cur = kt & 1;
        const bool more = (kt + 1 < ntiles);
        if (more) {
            const int k0 = (kt + 1) * BK;
            const float* ap = A + (size_t)(bm + ar) * K + k0 + ak;
            a0 = *(const float4*)ap;
            a1 = *(const float4*)(ap + (size_t)64 * K);
            if (TRANSB) {
                int gn = bn + tbN;
                bb = (gn < N) ? *(const float4*)(Bm + (size_t)gn * K + k0 + tbK)
                              : make_float4(0.f, 0.f, 0.f, 0.f);
            } else {
                bb = *(const float4*)(Bm + (size_t)(k0 + nbK) * N + bn + nbN);
            }
        }
        // ---- compute two k8 steps from stage `cur` ----
#pragma unroll
        for (int ks = 0; ks < 2; ks++) {
            const int k8 = ks * 8;
            unsigned af[2][4], bf[4][2];
#pragma unroll
            for (int i = 0; i < 2; i++) {
                const int mr = wm + i * 16 + g;
                af[i][0] = As[cur][mr    ][k8 + t];
                af[i][1] = As[cur][mr + 8][k8 + t];
                af[i][2] = As[cur][mr    ][k8 + t + 4];
                af[i][3] = As[cur][mr + 8][k8 + t + 4];
            }
#pragma unroll
            for (int j = 0; j < 4; j++) {
                const int nc = wn + j * 8 + g;
                if (TRANSB) {
                    bf[j][0] = Bs[cur][nc * 20 + k8 + t];
                    bf[j][1] = Bs[cur][nc * 20 + k8 + t + 4];
                } else {
                    bf[j][0] = Bs[cur][(k8 + t) * 68 + nc];
                    bf[j][1] = Bs[cur][(k8 + t + 4) * 68 + nc];
                }
            }
#pragma unroll
            for (int i = 0; i < 2; i++)
#pragma unroll
                for (int j = 0; j < 4; j++)
                    mma_tf32(acc[i][j], af[i], bf[j]);
        }
        if (more) {
            const int nxt = cur ^ 1;
            As[nxt][ar][ak+0] = f2tf(a0.x); As[nxt][ar][ak+1] = f2tf(a0.y);
            As[nxt][ar][ak+2] = f2tf(a0.z); As[nxt][ar][ak+3] = f2tf(a0.w);
            As[nxt][ar+64][ak+0] = f2tf(a1.x); As[nxt][ar+64][ak+1] = f2tf(a1.y);
            As[nxt][ar+64][ak+2] = f2tf(a1.z); As[nxt][ar+64][ak+3] = f2tf(a1.w);
            if (TRANSB) {
                unsigned* bp = &Bs[nxt][tbN * 20 + tbK];
                bp[0] = f2tf(bb.x); bp[1] = f2tf(bb.y);
                bp[2] = f2tf(bb.z); bp[3] = f2tf(bb.w);
            } else {
                Bs[nxt][nbK * 68 + nbN + 0] = f2tf(bb.x);
                Bs[nxt][nbK * 68 + nbN + 1] = f2tf(bb.y);
                Bs[nxt][nbK * 68 + nbN + 2] = f2tf(bb.z);
                Bs[nxt][nbK * 68 + nbN + 3] = f2tf(bb.w);
            }
        }
        __syncthreads();
    }

    // ---- epilogue ----
#pragma unroll
    for (int i = 0; i < 2; i++) {
        const int r0 = bm + wm + i * 16 + g;
        const int r1 = r0 + 8;
#pragma unroll
        for (int j = 0; j < 4; j++) {
            const int c = bn + wn + j * 8 + 2 * t;
            float v00 = acc[i][j][0], v01 = acc[i][j][1];
            float v10 = acc[i][j][2], v11 = acc[i][j][3];
            if (EPI & 1) {
                float b0 = bias[c], b1 = bias[c + 1];
                v00 += b0; v01 += b1; v10 += b0; v11 += b1;
            }
            if (EPI & 2) {
                v00 = gelu_exact(v00); v01 = gelu_exact(v01);
                v10 = gelu_exact(v10); v11 = gelu_exact(v11);
            }
            if (EPI & 4) {
                const float* rp0 = resid + (size_t)r0 * N + c;
                const float* rp1 = resid + (size_t)r1 * N + c;
                v00 += rp0[0]; v01 += rp0[1];
                v10 += rp1[0]; v11 += rp1[1];
            }
            if (!TRANSB) {
                float2 p0; p0.x = v00; p0.y = v01;
                float2 p1; p1.x = v10; p1.y = v11;
                *(float2*)(C + (size_t)r0 * N + c) = p0;
                *(float2*)(C + (size_t)r1 * N + c) = p1;
            } else {
                // N may be odd (V=50257): scalar bounds-checked stores
                if (c < N)     { C[(size_t)r0 * N + c]     = v00; C[(size_t)r1 * N + c]     = v10; }
                if (c + 1 < N) { C[(size_t)r0 * N + c + 1] = v01; C[(size_t)r1 * N + c + 1] = v11; }
            }
        }
    }
}

template <bool TRANSB, int EPI>
__global__ __launch_bounds__(256)
void tgemm_k(const float* __restrict__ A, const float* __restrict__ Bm,
             const float* __restrict__ bias, const float* __restrict__ resid,
             float* __restrict__ C, int N, int K) {
    tgemm_dev<TRANSB, EPI>(A, Bm, bias, resid, C, N, K,
                           blockIdx.y * 128, blockIdx.x * 64);
}

__global__ __launch_bounds__(256)
void qkv_k(const float* __restrict__ A,
           const float* __restrict__ Wq, const float* __restrict__ Wk,
           const float* __restrict__ Wv,
           float* __restrict__ q, float* __restrict__ k, float* __restrict__ v) {
    const float* Bm = (blockIdx.z == 0) ? Wq : (blockIdx.z == 1) ? Wk : Wv;
    float* C        = (blockIdx.z == 0) ? q  : (blockIdx.z == 1) ? k  : v;
    tgemm_dev<false, 0>(A, Bm, nullptr, nullptr, C, E_SZ, E_SZ,
                        blockIdx.y * 128, blockIdx.x * 64);
}

// ---------------- Causal attention (pair-split + chunked softmax) ----------
__global__ __launch_bounds__(128, 4)
void attn_kernel(const float* __restrict__ q, const float* __restrict__ k,
                 const float* __restrict__ v, float* __restrict__ o) {
    const int bh   = blockIdx.y;
    const int b    = bh / H_SZ, h = bh % H_SZ;
    const int ql   = threadIdx.x >> 1;
    const int half = threadIdx.x & 1;
    const int qi   = blockIdx.x * 64 + ql;
    const int hoff = h * D_SZ + half * 32;

    float qr[32];
    {
        const float* qp = q + ((size_t)(b * T_SZ + qi) * E_SZ) + hoff;
#pragma unroll
        for (int d = 0; d < 32; d += 4) {
            float4 t = *(const float4*)(qp + d);
            qr[d+0] = t.x * 0.125f; qr[d+1] = t.y * 0.125f;
            qr[d+2] = t.z * 0.125f; qr[d+3] = t.w * 0.125f;
        }
    }
    float m = -1e30f, l = 0.f;
    float accv[32];
#pragma unroll
    for (int d = 0; d < 32; d++) accv[d] = 0.f;

    __shared__ float Ks[64][68];
    __shared__ float Vs[64][68];

    const int qmax = blockIdx.x * 64 + 63;
    for (int kt = 0; kt <= qmax; kt += 64) {
#pragma unroll
        for (int i = 0; i < 8; i++) {
            int f   = threadIdx.x + i * 128;
            int rr  = f >> 4;
            int cc  = (f & 15) * 4;
            size_t gb = ((size_t)(b * T_SZ + kt + rr) * E_SZ) + h * D_SZ + cc;
            *(float4*)&Ks[rr][cc] = *(const float4*)(k + gb);
            *(float4*)&Vs[rr][cc] = *(const float4*)(v + gb);
        }
        __syncthreads();

        const int kend = min(qi - kt + 1, 64);
        for (int c0 = 0; c0 < 64; c0 += 16) {
            if (c0 >= kend) break;
            float s[16];
#pragma unroll
            for (int j = 0; j < 16; j++) {
                float a0 = 0.f, a1 = 0.f;
#pragma unroll
                for (int d = 0; d < 32; d += 8) {
                    float4 k0 = *(const float4*)&Ks[c0 + j][half * 32 + d];
                    float4 k1 = *(const float4*)&Ks[c0 + j][half * 32 + d + 4];
                    a0 += qr[d+0]*k0.x + qr[d+1]*k0.y + qr[d+2]*k0.z + qr[d+3]*k0.w;
                    a1 += qr[d+4]*k1.x + qr[d+5]*k1.y + qr[d+6]*k1.z + qr[d+7]*k1.w;
                }
                s[j] = a0 + a1;
            }
#pragma unroll
            for (int j = 0; j < 16; j++) {
                s[j] += __shfl_xor_sync(0xffffffffu, s[j], 1);
                if (c0 + j >= kend) s[j] = -1e30f;
            }
            float cm = s[0];
#pragma unroll
            for (int j = 1; j < 16; j++) cm = fmaxf(cm, s[j]);
            float mn = fmaxf(m, cm);
            float cf = __expf(m - mn);
            m = mn;
#pragma unroll
            for (int d = 0; d < 32; d++) accv[d] *= cf;
            float ps = 0.f;
#pragma unroll
            for (int j = 0; j < 16; j++) {
                float p = __expf(s[j] - mn);
                ps += p;
#pragma unroll
                for (int d = 0; d < 32; d += 4) {
                    float4 vv = *(const float4*)&Vs[c0 + j][half * 32 + d];
                    accv[d+0] += p * vv.x; accv[d+1] += p * vv.y;
                    accv[d+2] += p * vv.z; accv[d+3] += p * vv.w;
                }
            }
            l = l * cf + ps;
        }
        __syncthreads();
    }
    const float inv = 1.f / l;
    float* op = o + ((size_t)(b * T_SZ + qi) * E_SZ) + hoff;
#pragma unroll
    for (int d = 0; d < 32; d += 4) {
        float4 t;
        t.x = accv[d+0] * inv; t.y = accv[d+1] * inv;
        t.z = accv[d+2] * inv; t.w = accv[d+3] * inv;
        *(float4*)(op + d) = t;
    }
}

// ---------------- Host orchestration ----------------
extern "C" void kernel_launch(void* const* d_in, const int* in_sizes, int n_in,
                              void* d_out, int out_size) {
    (void)in_sizes; (void)n_in; (void)out_size;
    const int*   tokens = (const int*)  d_in[0];
    const float* wte    = (const float*)d_in[1];
    const float* wpe    = (const float*)d_in[2];
    const float* Wq     = (const float*)d_in[3];
    const float* Wk     = (const float*)d_in[4];
    const float* Wv     = (const float*)d_in[5];
    const float* Wo     = (const float*)d_in[6];
    const float* bo     = (const float*)d_in[7];
    const float* ln1_s  = (const float*)d_in[8];
    const float* ln1_b  = (const float*)d_in[9];
    const float* W1     = (const float*)d_in[10];
    const float* b1     = (const float*)d_in[11];
    const float* W2     = (const float*)d_in[12];
    const float* b2     = (const float*)d_in[13];
    const float* ln2_s  = (const float*)d_in[14];
    const float* ln2_b  = (const float*)d_in[15];
    const float* lnf_s  = (const float*)d_in[16];
    const float* lnf_b  = (const float*)d_in[17];
    float* out = (float*)d_out;

    float *x, *h, *q, *k, *v, *att, *m1;
    cudaGetSymbolAddress((void**)&x,   g_x);
    cudaGetSymbolAddress((void**)&h,   g_h);
    cudaGetSymbolAddress((void**)&q,   g_q);
    cudaGetSymbolAddress((void**)&k,   g_k);
    cudaGetSymbolAddress((void**)&v,   g_v);
    cudaGetSymbolAddress((void**)&att, g_att);
    cudaGetSymbolAddress((void**)&m1,  g_m1);

    embed_kernel<<<BT, 192>>>(tokens, wte, wpe, x);

    const dim3 gE(E_SZ / 64, BT / 128);          // 12 x 16 = 192
    const dim3 gQKV(E_SZ / 64, BT / 128, 3);     // 576
    const dim3 gF(FF / 64, BT / 128);            // 48 x 16 = 768
    const dim3 gATT(T_SZ / 64, B_SZ * H_SZ);     // 384
    const dim3 gLOG((V_SZ + 63) / 64, BT / 128); // 786 x 16

    for (int l = 0; l < L_SZ; l++) {
        const size_t wOff  = (size_t)l * E_SZ * E_SZ;
        const size_t w1Off = (size_t)l * E_SZ * FF;
        const size_t vOff  = (size_t)l * E_SZ;
        const size_t fOff  = (size_t)l * FF;

        layernorm_kernel<<<BT, 256>>>(x, ln1_s + vOff, ln1_b + vOff, h);
        qkv_k<<<gQKV, 256>>>(h, Wq + wOff, Wk + wOff, Wv + wOff, q, k, v);
        attn_kernel<<<gATT, 128>>>(q, k, v, att);
        tgemm_k<false, 5><<<gE, 256>>>(att, Wo + wOff, bo + vOff, x, x, E_SZ, E_SZ);
        layernorm_kernel<<<BT, 256>>>(x, ln2_s + vOff, ln2_b + vOff, h);
        tgemm_k<false, 3><<<gF, 256>>>(h, W1 + w1Off, b1 + fOff, nullptr, m1, FF, E_SZ);
        tgemm_k<false, 5><<<gE, 256>>>(m1, W2 + w1Off, b2 + vOff, x, x, E_SZ, FF);
    }

    layernorm_kernel<<<BT, 256>>>(x, lnf_s, lnf_b, h);
    tgemm_k<true, 0><<<gLOG, 256>>>(h, wte, nullptr, nullptr, out, V_SZ, E_SZ);
}

// round 6
// speedup vs baseline: 2.6507x; 1.1629x over previous
#include <cuda_runtime.h>
#include <cuda_bf16.h>
#include <math.h>

// ---------------- Problem constants ----------------
#define V_SZ 50257
#define E_SZ 768
#define H_SZ 12
#define L_SZ 6
#define T_SZ 1024
#define B_SZ 2
#define D_SZ 64
#define BT   (B_SZ * T_SZ)      // 2048
#define FF   (4 * E_SZ)         // 3072

// ---------------- Scratch (device globals; no allocations allowed) ----------
__device__ float g_x  [BT * E_SZ];
__device__ float g_h  [BT * E_SZ];
__device__ float g_q  [BT * E_SZ];
__device__ float g_k  [BT * E_SZ];
__device__ float g_v  [BT * E_SZ];
__device__ float g_att[BT * E_SZ];
__device__ float g_m1 [BT * FF];

// ---------------- Embedding ----------------
__global__ void embed_kernel(const int* __restrict__ tok,
                             const float* __restrict__ wte,
                             const float* __restrict__ wpe,
                             float* __restrict__ x) {
    int row = blockIdx.x;
    int t   = row % T_SZ;
    int tk  = tok[row];
    int e   = threadIdx.x * 4;
    const float4 a = *(const float4*)(wte + (size_t)tk * E_SZ + e);
    const float4 b = *(const float4*)(wpe + (size_t)t  * E_SZ + e);
    float4 o;
    o.x = a.x + b.x; o.y = a.y + b.y; o.z = a.z + b.z; o.w = a.w + b.w;
    *(float4*)(x + (size_t)row * E_SZ + e) = o;
}

// ---------------- LayerNorm ----------------
__global__ void layernorm_kernel(const float* __restrict__ x,
                                 const float* __restrict__ sc,
                                 const float* __restrict__ bi,
                                 float* __restrict__ out) {
    int row = blockIdx.x;
    const float* xr = x + (size_t)row * E_SZ;
    float lv[3];
    float s = 0.f, sq = 0.f;
#pragma unroll
    for (int i = 0; i < 3; i++) {
        float t = xr[threadIdx.x + i * 256];
        lv[i] = t; s += t; sq += t * t;
    }
#pragma unroll
    for (int o = 16; o > 0; o >>= 1) {
        s  += __shfl_down_sync(0xffffffffu, s,  o);
        sq += __shfl_down_sync(0xffffffffu, sq, o);
    }
    __shared__ float sa[8], sb[8];
    int w = threadIdx.x >> 5, lane = threadIdx.x & 31;
    if (lane == 0) { sa[w] = s; sb[w] = sq; }
    __syncthreads();
    __shared__ float s_mu, s_rstd;
    if (threadIdx.x == 0) {
        float ts = 0.f, tq = 0.f;
#pragma unroll
        for (int i = 0; i < 8; i++) { ts += sa[i]; tq += sb[i]; }
        float mu  = ts * (1.0f / E_SZ);
        float var = tq * (1.0f / E_SZ) - mu * mu;
        s_mu = mu;
        s_rstd = rsqrtf(var + 1e-5f);
    }
    __syncthreads();
    float mu = s_mu, rstd = s_rstd;
#pragma unroll
    for (int i = 0; i < 3; i++) {
        int c = threadIdx.x + i * 256;
        out[(size_t)row * E_SZ + c] = (lv[i] - mu) * rstd * sc[c] + bi[c];
    }
}

// ---------------- TF32 tensor-core GEMM ----------------
__device__ __forceinline__ float gelu_exact(float v) {
    return 0.5f * v * (1.0f + erff(v * 0.70710678118654752f));
}
__device__ __forceinline__ unsigned f2tf(float f) {
    unsigned u;
    asm("cvt.rna.tf32.f32 %0, %1;" : "=r"(u) : "f"(f));
    return u;
}
__device__ __forceinline__ void mma_tf32(float* d, const unsigned* a, const unsigned* b) {
    asm volatile(
        "mma.sync.aligned.m16n8k8.row.col.f32.tf32.tf32.f32 "
        "{%0,%1,%2,%3}, {%4,%5,%6,%7}, {%8,%9}, {%0,%1,%2,%3};"
        : "+f"(d[0]), "+f"(d[1]), "+f"(d[2]), "+f"(d[3])
        : "r"(a[0]), "r"(a[1]), "r"(a[2]), "r"(a[3]), "r"(b[0]), "r"(b[1]));
}

template <bool TRANSB, int EPI>
__device__ __forceinline__
void tgemm_dev(const float* __restrict__ A, const float* __restrict__ Bm,
               const float* __restrict__ bias, const float* __restrict__ resid,
               float* __restrict__ C, int N, int K, int bm, int bn) {
    constexpr int BK = 16;
    __shared__ unsigned As[2][128][20];
    __shared__ unsigned Bs[2][TRANSB ? (64 * 20) : (16 * 68)];

    const int tid  = threadIdx.x;
    const int lane = tid & 31;
    const int wid  = tid >> 5;
    const int wm   = (wid & 3) * 32;
    const int wn   = (wid >> 2) * 32;
    const int g    = lane >> 2;
    const int t    = lane & 3;

    float acc[2][4][4];
#pragma unroll
    for (int i = 0; i < 2; i++)
#pragma unroll
        for (int j = 0; j < 4; j++)
#pragma unroll
            for (int r = 0; r < 4; r++) acc[i][j][r] = 0.f;

    const int ar = tid >> 2;
    const int ak = (tid & 3) * 4;
    const int nbK = tid >> 4;
    const int nbN = (tid & 15) * 4;
    const int tbN = tid >> 2;
    const int tbK = (tid & 3) * 4;

    const int ntiles = K / BK;
    float4 a0, a1, bb;

    {
        const float* ap = A + (size_t)(bm + ar) * K + ak;
        a0 = *(const float4*)ap;
        a1 = *(const float4*)(ap + (size_t)64 * K);
        if (TRANSB) {
            int gn = bn + tbN;
            bb = (gn < N) ? *(const float4*)(Bm + (size_t)gn * K + tbK)
                          : make_float4(0.f, 0.f, 0.f, 0.f);
        } else {
            bb = *(const float4*)(Bm + (size_t)nbK * N + bn + nbN);
        }
        As[0][ar][ak+0] = f2tf(a0.x); As[0][ar][ak+1] = f2tf(a0.y);
        As[0][ar][ak+2] = f2tf(a0.z); As[0][ar][ak+3] = f2tf(a0.w);
        As[0][ar+64][ak+0] = f2tf(a1.x); As[0][ar+64][ak+1] = f2tf(a1.y);
        As[0][ar+64][ak+2] = f2tf(a1.z); As[0][ar+64][ak+3] = f2tf(a1.w);
        if (TRANSB) {
            unsigned* bp = &Bs[0][tbN * 20 + tbK];
            bp[0] = f2tf(bb.x); bp[1] = f2tf(bb.y);
            bp[2] = f2tf(bb.z); bp[3] = f2tf(bb.w);
        } else {
            Bs[0][nbK * 68 + nbN + 0] = f2tf(bb.x);
            Bs[0][nbK * 68 + nbN + 1] = f2tf(bb.y);
            Bs[0][nbK * 68 + nbN + 2] = f2tf(bb.z);
            Bs[0][nbK * 68 + nbN + 3] = f2tf(bb.w);
        }
    }
    __syncthreads();

    for (int kt = 0; kt < ntiles; kt++) {
        const int cur = kt & 1;
        const bool more = (kt + 1 < ntiles);
        if (more) {
            const int k0 = (kt + 1) * BK;
            const float* ap = A + (size_t)(bm + ar) * K + k0 + ak;
            a0 = *(const float4*)ap;
            a1 = *(const float4*)(ap + (size_t)64 * K);
            if (TRANSB) {
                int gn = bn + tbN;
                bb = (gn < N) ? *(const float4*)(Bm + (size_t)gn * K + k0 + tbK)
                              : make_float4(0.f, 0.f, 0.f, 0.f);
            } else {
                bb = *(const float4*)(Bm + (size_t)(k0 + nbK) * N + bn + nbN);
            }
        }
#pragma unroll
        for (int ks = 0; ks < 2; ks++) {
            const int k8 = ks * 8;
            unsigned af[2][4], bf[4][2];
#pragma unroll
            for (int i = 0; i < 2; i++) {
                const int mr = wm + i * 16 + g;
                af[i][0] = As[cur][mr    ][k8 + t];
                af[i][1] = As[cur][mr + 8][k8 + t];
                af[i][2] = As[cur][mr    ][k8 + t + 4];
                af[i][3] = As[cur][mr + 8][k8 + t + 4];
            }
#pragma unroll
            for (int j = 0; j < 4; j++) {
                const int nc = wn + j * 8 + g;
                if (TRANSB) {
                    bf[j][0] = Bs[cur][nc * 20 + k8 + t];
                    bf[j][1] = Bs[cur][nc * 20 + k8 + t + 4];
                } else {
                    bf[j][0] = Bs[cur][(k8 + t) * 68 + nc];
                    bf[j][1] = Bs[cur][(k8 + t + 4) * 68 + nc];
                }
            }
#pragma unroll
            for (int i = 0; i < 2; i++)
#pragma unroll
                for (int j = 0; j < 4; j++)
                    mma_tf32(acc[i][j], af[i], bf[j]);
        }
        if (more) {
            const int nxt = cur ^ 1;
            As[nxt][ar][ak+0] = f2tf(a0.x); As[nxt][ar][ak+1] = f2tf(a0.y);
            As[nxt][ar][ak+2] = f2tf(a0.z); As[nxt][ar][ak+3] = f2tf(a0.w);
            As[nxt][ar+64][ak+0] = f2tf(a1.x); As[nxt][ar+64][ak+1] = f2tf(a1.y);
            As[nxt][ar+64][ak+2] = f2tf(a1.z); As[nxt][ar+64][ak+3] = f2tf(a1.w);
            if (TRANSB) {
                unsigned* bp = &Bs[nxt][tbN * 20 + tbK];
                bp[0] = f2tf(bb.x); bp[1] = f2tf(bb.y);
                bp[2] = f2tf(bb.z); bp[3] = f2tf(bb.w);
            } else {
                Bs[nxt][nbK * 68 + nbN + 0] = f2tf(bb.x);
                Bs[nxt][nbK * 68 + nbN + 1] = f2tf(bb.y);
                Bs[nxt][nbK * 68 + nbN + 2] = f2tf(bb.z);
                Bs[nxt][nbK * 68 + nbN + 3] = f2tf(bb.w);
            }
        }
        __syncthreads();
    }

#pragma unroll
    for (int i = 0; i < 2; i++) {
        const int r0 = bm + wm + i * 16 + g;
        const int r1 = r0 + 8;
#pragma unroll
        for (int j = 0; j < 4; j++) {
            const int c = bn + wn + j * 8 + 2 * t;
            float v00 = acc[i][j][0], v01 = acc[i][j][1];
            float v10 = acc[i][j][2], v11 = acc[i][j][3];
            if (EPI & 1) {
                float b0 = bias[c], b1 = bias[c + 1];
                v00 += b0; v01 += b1; v10 += b0; v11 += b1;
            }
            if (EPI & 2) {
                v00 = gelu_exact(v00); v01 = gelu_exact(v01);
                v10 = gelu_exact(v10); v11 = gelu_exact(v11);
            }
            if (EPI & 4) {
                const float* rp0 = resid + (size_t)r0 * N + c;
                const float* rp1 = resid + (size_t)r1 * N + c;
                v00 += rp0[0]; v01 += rp0[1];
                v10 += rp1[0]; v11 += rp1[1];
            }
            if (!TRANSB) {
                float2 p0; p0.x = v00; p0.y = v01;
                float2 p1; p1.x = v10; p1.y = v11;
                *(float2*)(C + (size_t)r0 * N + c) = p0;
                *(float2*)(C + (size_t)r1 * N + c) = p1;
            } else {
                if (c < N)     { C[(size_t)r0 * N + c]     = v00; C[(size_t)r1 * N + c]     = v10; }
                if (c + 1 < N) { C[(size_t)r0 * N + c + 1] = v01; C[(size_t)r1 * N + c + 1] = v11; }
            }
        }
    }
}

template <bool TRANSB, int EPI>
__global__ __launch_bounds__(256)
void tgemm_k(const float* __restrict__ A, const float* __restrict__ Bm,
             const float* __restrict__ bias, const float* __restrict__ resid,
             float* __restrict__ C, int N, int K) {
    tgemm_dev<TRANSB, EPI>(A, Bm, bias, resid, C, N, K,
                           blockIdx.y * 128, blockIdx.x * 64);
}

__global__ __launch_bounds__(256)
void qkv_k(const float* __restrict__ A,
           const float* __restrict__ Wq, const float* __restrict__ Wk,
           const float* __restrict__ Wv,
           float* __restrict__ q, float* __restrict__ k, float* __restrict__ v) {
    const float* Bm = (blockIdx.z == 0) ? Wq : (blockIdx.z == 1) ? Wk : Wv;
    float* C        = (blockIdx.z == 0) ? q  : (blockIdx.z == 1) ? k  : v;
    tgemm_dev<false, 0>(A, Bm, nullptr, nullptr, C, E_SZ, E_SZ,
                        blockIdx.y * 128, blockIdx.x * 64);
}

// ---------------- Causal attention v3: flash tile, fp32 register GEMMs -----
// 256 threads (16x16). S tile 64x64 (4x4/thread), O tile 64x64 (4x4/thread).
// Softmax in registers via half-warp shuffles; P staged through smem for PV.
#define ATTN_SMEM (4 * 64 * 68 * 4 + 2 * 64 * 4)

__global__ __launch_bounds__(256)
void attn_kernel(const float* __restrict__ q, const float* __restrict__ k,
                 const float* __restrict__ v, float* __restrict__ o) {
    extern __shared__ float sm[];
    float (*Qs)[68] = (float(*)[68])(sm);              // [d][q] transposed
    float (*Ks)[68] = (float(*)[68])(sm + 64 * 68);    // [d][k] transposed
    float (*Vs)[68] = (float(*)[68])(sm + 2 * 64 * 68);// [k][d] natural
    float (*Ss)[68] = (float(*)[68])(sm + 3 * 64 * 68);// [q][k] P matrix
    float* ms = sm + 4 * 64 * 68;                      // row max
    float* ls = ms + 64;                               // row sum

    const int bh  = blockIdx.y;
    const int b   = bh / H_SZ, h = bh % H_SZ;
    const int q0  = blockIdx.x * 64;
    const int tid = threadIdx.x;
    const int tx  = tid & 15, ty = tid >> 4;

    // load Q transposed & pre-scaled (consecutive lanes -> consecutive smem addr)
#pragma unroll
    for (int i = 0; i < 4; i++) {
        int f  = tid + i * 256;
        int qq = f & 63, d4 = (f >> 6) * 4;
        float4 t = *(const float4*)(q + ((size_t)(b * T_SZ + q0 + qq) * E_SZ) + h * D_SZ + d4);
        Qs[d4+0][qq] = t.x * 0.125f; Qs[d4+1][qq] = t.y * 0.125f;
        Qs[d4+2][qq] = t.z * 0.125f; Qs[d4+3][qq] = t.w * 0.125f;
    }
    if (tid < 64) { ms[tid] = -1e30f; ls[tid] = 0.f; }

    float acc[4][4];
#pragma unroll
    for (int r = 0; r < 4; r++)
#pragma unroll
        for (int c = 0; c < 4; c++) acc[r][c] = 0.f;

    for (int kt = 0; kt <= q0; kt += 64) {
        // K transposed
#pragma unroll
        for (int i = 0; i < 4; i++) {
            int f  = tid + i * 256;
            int kk = f & 63, d4 = (f >> 6) * 4;
            float4 t = *(const float4*)(k + ((size_t)(b * T_SZ + kt + kk) * E_SZ) + h * D_SZ + d4);
            Ks[d4+0][kk] = t.x; Ks[d4+1][kk] = t.y;
            Ks[d4+2][kk] = t.z; Ks[d4+3][kk] = t.w;
        }
        // V natural
#pragma unroll
        for (int i = 0; i < 4; i++) {
            int f  = tid + i * 256;
            int kk = f >> 4, d4 = (f & 15) * 4;
            *(float4*)&Vs[kk][d4] =
                *(const float4*)(v + ((size_t)(b * T_SZ + kt + kk) * E_SZ) + h * D_SZ + d4);
        }
        __syncthreads();

        // ---- S = Q K^T (register tile 4x4) ----
        float s[4][4];
#pragma unroll
        for (int r = 0; r < 4; r++)
#pragma unroll
            for (int c = 0; c < 4; c++) s[r][c] = 0.f;
#pragma unroll 4
        for (int d = 0; d < 64; d++) {
            float4 aq = *(const float4*)&Qs[d][4 * ty];
            float4 bk = *(const float4*)&Ks[d][4 * tx];
            float a[4] = {aq.x, aq.y, aq.z, aq.w};
            float bb[4] = {bk.x, bk.y, bk.z, bk.w};
#pragma unroll
            for (int r = 0; r < 4; r++)
#pragma unroll
                for (int c = 0; c < 4; c++) s[r][c] += a[r] * bb[c];
        }

        // ---- softmax in registers (row = half-warp) ----
        const bool diag = (kt == q0);
        float cfl[4];
#pragma unroll
        for (int r = 0; r < 4; r++) {
            const int row = 4 * ty + r;
            if (diag) {
#pragma unroll
                for (int c = 0; c < 4; c++)
                    if (4 * tx + c > row) s[r][c] = -1e30f;
            }
            float mx = fmaxf(fmaxf(s[r][0], s[r][1]), fmaxf(s[r][2], s[r][3]));
#pragma unroll
            for (int off = 1; off < 16; off <<= 1)
                mx = fmaxf(mx, __shfl_xor_sync(0xffffffffu, mx, off));
            const float mold = ms[row];
            const float mnew = fmaxf(mold, mx);
            float ps = 0.f;
#pragma unroll
            for (int c = 0; c < 4; c++) {
                float p = __expf(s[r][c] - mnew);
                Ss[row][4 * tx + c] = p;
                ps += p;
            }
#pragma unroll
            for (int off = 1; off < 16; off <<= 1)
                ps += __shfl_xor_sync(0xffffffffu, ps, off);
            cfl[r] = __expf(mold - mnew);
            if (tx == 0) { ms[row] = mnew; ls[row] = ls[row] * cfl[r] + ps; }
        }
        __syncthreads();

        // ---- O = O*cf + P V (register tile 4x4) ----
#pragma unroll
        for (int r = 0; r < 4; r++)
#pragma unroll
            for (int c = 0; c < 4; c++) acc[r][c] *= cfl[r];
#pragma unroll 4
        for (int kk = 0; kk < 64; kk++) {
            float4 vv = *(const float4*)&Vs[kk][4 * tx];
#pragma unroll
            for (int r = 0; r < 4; r++) {
                float p = Ss[4 * ty + r][kk];
                acc[r][0] += p * vv.x; acc[r][1] += p * vv.y;
                acc[r][2] += p * vv.z; acc[r][3] += p * vv.w;
            }
        }
        __syncthreads();
    }

    // ---- epilogue ----
#pragma unroll
    for (int r = 0; r < 4; r++) {
        const float inv = 1.f / ls[4 * ty + r];
        float4 t;
        t.x = acc[r][0] * inv; t.y = acc[r][1] * inv;
        t.z = acc[r][2] * inv; t.w = acc[r][3] * inv;
        *(float4*)(o + ((size_t)(b * T_SZ + q0 + 4 * ty + r) * E_SZ) + h * D_SZ + 4 * tx) = t;
    }
}

// ---------------- Host orchestration ----------------
extern "C" void kernel_launch(void* const* d_in, const int* in_sizes, int n_in,
                              void* d_out, int out_size) {
    (void)in_sizes; (void)n_in; (void)out_size;
    const int*   tokens = (const int*)  d_in[0];
    const float* wte    = (const float*)d_in[1];
    const float* wpe    = (const float*)d_in[2];
    const float* Wq     = (const float*)d_in[3];
    const float* Wk     = (const float*)d_in[4];
    const float* Wv     = (const float*)d_in[5];
    const float* Wo     = (const float*)d_in[6];
    const float* bo     = (const float*)d_in[7];
    const float* ln1_s  = (const float*)d_in[8];
    const float* ln1_b  = (const float*)d_in[9];
    const float* W1     = (const float*)d_in[10];
    const float* b1     = (const float*)d_in[11];
    const float* W2     = (const float*)d_in[12];
    const float* b2     = (const float*)d_in[13];
    const float* ln2_s  = (const float*)d_in[14];
    const float* ln2_b  = (const float*)d_in[15];
    const float* lnf_s  = (const float*)d_in[16];
    const float* lnf_b  = (const float*)d_in[17];
    float* out = (float*)d_out;

    float *x, *h, *q, *k, *v, *att, *m1;
    cudaGetSymbolAddress((void**)&x,   g_x);
    cudaGetSymbolAddress((void**)&h,   g_h);
    cudaGetSymbolAddress((void**)&q,   g_q);
    cudaGetSymbolAddress((void**)&k,   g_k);
    cudaGetSymbolAddress((void**)&v,   g_v);
    cudaGetSymbolAddress((void**)&att, g_att);
    cudaGetSymbolAddress((void**)&m1,  g_m1);

    // allow >48KB dynamic smem for attention (host-side config; capture-safe)
    cudaFuncSetAttribute(attn_kernel,
                         cudaFuncAttributeMaxDynamicSharedMemorySize, ATTN_SMEM);

    embed_kernel<<<BT, 192>>>(tokens, wte, wpe, x);

    const dim3 gE(E_SZ / 64, BT / 128);          // 12 x 16 = 192
    const dim3 gQKV(E_SZ / 64, BT / 128, 3);     // 576
    const dim3 gF(FF / 64, BT / 128);            // 48 x 16 = 768
    const dim3 gATT(T_SZ / 64, B_SZ * H_SZ);     // 16 x 24 = 384
    const dim3 gLOG((V_SZ + 63) / 64, BT / 128); // 786 x 16

    for (int l = 0; l < L_SZ; l++) {
        const size_t wOff  = (size_t)l * E_SZ * E_SZ;
        const size_t w1Off = (size_t)l * E_SZ * FF;
        const size_t vOff  = (size_t)l * E_SZ;
        const size_t fOff  = (size_t)l * FF;

        layernorm_kernel<<<BT, 256>>>(x, ln1_s + vOff, ln1_b + vOff, h);
        qkv_k<<<gQKV, 256>>>(h, Wq + wOff, Wk + wOff, Wv + wOff, q, k, v);
        attn_kernel<<<gATT, 256, ATTN_SMEM>>>(q, k, v, att);
        tgemm_k<false, 5><<<gE, 256>>>(att, Wo + wOff, bo + vOff, x, x, E_SZ, E_SZ);
        layernorm_kernel<<<BT, 256>>>(x, ln2_s + vOff, ln2_b + vOff, h);
        tgemm_k<false, 3><<<gF, 256>>>(h, W1 + w1Off, b1 + fOff, nullptr, m1, FF, E_SZ);
        tgemm_k<false, 5><<<gE, 256>>>(m1, W2 + w1Off, b2 + vOff, x, x, E_SZ, FF);
    }

    layernorm_kernel<<<BT, 256>>>(x, lnf_s, lnf_b, h);
    tgemm_k<true, 0><<<gLOG, 256>>>(h, wte, nullptr, nullptr, out, V_SZ, E_SZ);
}

// round 7
// speedup vs baseline: 2.7401x; 1.0337x over previous
#include <cuda_runtime.h>
#include <cuda_bf16.h>
#include <math.h>

// ---------------- Problem constants ----------------
#define V_SZ 50257
#define E_SZ 768
#define H_SZ 12
#define L_SZ 6
#define T_SZ 1024
#define B_SZ 2
#define D_SZ 64
#define BT   (B_SZ * T_SZ)      // 2048
#define FF   (4 * E_SZ)         // 3072

// ---------------- Scratch (device globals; no allocations allowed) ----------
__device__ float g_x  [BT * E_SZ];
__device__ float g_h  [BT * E_SZ];
__device__ float g_q  [BT * E_SZ];
__device__ float g_k  [BT * E_SZ];
__device__ float g_v  [BT * E_SZ];
__device__ float g_att[BT * E_SZ];
__device__ float g_m1 [BT * FF];

// ---------------- Embedding ----------------
__global__ void embed_kernel(const int* __restrict__ tok,
                             const float* __restrict__ wte,
                             const float* __restrict__ wpe,
                             float* __restrict__ x) {
    int row = blockIdx.x;
    int t   = row % T_SZ;
    int tk  = tok[row];
    int e   = threadIdx.x * 4;
    const float4 a = *(const float4*)(wte + (size_t)tk * E_SZ + e);
    const float4 b = *(const float4*)(wpe + (size_t)t  * E_SZ + e);
    float4 o;
    o.x = a.x + b.x; o.y = a.y + b.y; o.z = a.z + b.z; o.w = a.w + b.w;
    *(float4*)(x + (size_t)row * E_SZ + e) = o;
}

// ---------------- LayerNorm ----------------
__global__ void layernorm_kernel(const float* __restrict__ x,
                                 const float* __restrict__ sc,
                                 const float* __restrict__ bi,
                                 float* __restrict__ out) {
    int row = blockIdx.x;
    const float* xr = x + (size_t)row * E_SZ;
    float lv[3];
    float s = 0.f, sq = 0.f;
#pragma unroll
    for (int i = 0; i < 3; i++) {
        float t = xr[threadIdx.x + i * 256];
        lv[i] = t; s += t; sq += t * t;
    }
#pragma unroll
    for (int o = 16; o > 0; o >>= 1) {
        s  += __shfl_down_sync(0xffffffffu, s,  o);
        sq += __shfl_down_sync(0xffffffffu, sq, o);
    }
    __shared__ float sa[8], sb[8];
    int w = threadIdx.x >> 5, lane = threadIdx.x & 31;
    if (lane == 0) { sa[w] = s; sb[w] = sq; }
    __syncthreads();
    __shared__ float s_mu, s_rstd;
    if (threadIdx.x == 0) {
        float ts = 0.f, tq = 0.f;
#pragma unroll
        for (int i = 0; i < 8; i++) { ts += sa[i]; tq += sb[i]; }
        float mu  = ts * (1.0f / E_SZ);
        float var = tq * (1.0f / E_SZ) - mu * mu;
        s_mu = mu;
        s_rstd = rsqrtf(var + 1e-5f);
    }
    __syncthreads();
    float mu = s_mu, rstd = s_rstd;
#pragma unroll
    for (int i = 0; i < 3; i++) {
        int c = threadIdx.x + i * 256;
        out[(size_t)row * E_SZ + c] = (lv[i] - mu) * rstd * sc[c] + bi[c];
    }
}

// ---------------- TF32 tensor-core GEMM ----------------
// BM=128, BN=64 or 128, BK=16, double-buffered.
// 8 warps: 4 (m) x 2 (n); warp tile 32 x (BN/2).
// Grid mapping: blockIdx.x = m-block (few), blockIdx.y = n-block (many),
// so consecutive CTAs share the same B tile (L2 reuse for big B).
__device__ __forceinline__ float gelu_exact(float v) {
    return 0.5f * v * (1.0f + erff(v * 0.70710678118654752f));
}
__device__ __forceinline__ unsigned f2tf(float f) {
    unsigned u;
    asm("cvt.rna.tf32.f32 %0, %1;" : "=r"(u) : "f"(f));
    return u;
}
__device__ __forceinline__ void mma_tf32(float* d, const unsigned* a, const unsigned* b) {
    asm volatile(
        "mma.sync.aligned.m16n8k8.row.col.f32.tf32.tf32.f32 "
        "{%0,%1,%2,%3}, {%4,%5,%6,%7}, {%8,%9}, {%0,%1,%2,%3};"
        : "+f"(d[0]), "+f"(d[1]), "+f"(d[2]), "+f"(d[3])
        : "r"(a[0]), "r"(a[1]), "r"(a[2]), "r"(a[3]), "r"(b[0]), "r"(b[1]));
}

template <int BN, bool TRANSB, int EPI>
__device__ __forceinline__
void tgemm_dev(const float* __restrict__ A, const float* __restrict__ Bm,
               const float* __restrict__ bias, const float* __restrict__ resid,
               float* __restrict__ C, int N, int K, int bm, int bn) {
    constexpr int BK = 16;
    constexpr int NJ = BN / 16;               // n8 atoms per warp: 4 or 8
    constexpr int BROW = BN + 4;              // non-trans B smem row stride
    __shared__ unsigned As[2][128][20];
    __shared__ unsigned Bs[2][TRANSB ? (BN * 20) : (BK * BROW)];

    const int tid  = threadIdx.x;
    const int lane = tid & 31;
    const int wid  = tid >> 5;
    const int wm   = (wid & 3) * 32;
    const int wn   = (wid >> 2) * (BN / 2);
    const int g    = lane >> 2;
    const int t    = lane & 3;

    float acc[2][NJ][4];
#pragma unroll
    for (int i = 0; i < 2; i++)
#pragma unroll
        for (int j = 0; j < NJ; j++)
#pragma unroll
            for (int r = 0; r < 4; r++) acc[i][j][r] = 0.f;

    const int ar = tid >> 2;
    const int ak = (tid & 3) * 4;
    const int nbK = tid >> 4;
    const int nbN = (tid & 15) * 4;
    const int tbN = tid >> 2;
    const int tbK = (tid & 3) * 4;

    const int ntiles = K / BK;
    float4 a0, a1, b0, b1;

    // ---- prologue: tile 0 global loads + stage ----
    {
        const float* ap = A + (size_t)(bm + ar) * K + ak;
        a0 = *(const float4*)ap;
        a1 = *(const float4*)(ap + (size_t)64 * K);
        if (TRANSB) {
            int gn0 = bn + tbN;
            b0 = (gn0 < N) ? *(const float4*)(Bm + (size_t)gn0 * K + tbK)
                           : make_float4(0.f, 0.f, 0.f, 0.f);
            if (BN == 128) {
                int gn1 = gn0 + 64;
                b1 = (gn1 < N) ? *(const float4*)(Bm + (size_t)gn1 * K + tbK)
                               : make_float4(0.f, 0.f, 0.f, 0.f);
            }
        } else {
            const float* bp = Bm + (size_t)nbK * N + bn + nbN;
            b0 = *(const float4*)bp;
            if (BN == 128) b1 = *(const float4*)(bp + 64);
        }
        As[0][ar][ak+0] = f2tf(a0.x); As[0][ar][ak+1] = f2tf(a0.y);
        As[0][ar][ak+2] = f2tf(a0.z); As[0][ar][ak+3] = f2tf(a0.w);
        As[0][ar+64][ak+0] = f2tf(a1.x); As[0][ar+64][ak+1] = f2tf(a1.y);
        As[0][ar+64][ak+2] = f2tf(a1.z); As[0][ar+64][ak+3] = f2tf(a1.w);
        if (TRANSB) {
            unsigned* bp = &Bs[0][tbN * 20 + tbK];
            bp[0] = f2tf(b0.x); bp[1] = f2tf(b0.y);
            bp[2] = f2tf(b0.z); bp[3] = f2tf(b0.w);
            if (BN == 128) {
                unsigned* bq = &Bs[0][(tbN + 64) * 20 + tbK];
                bq[0] = f2tf(b1.x); bq[1] = f2tf(b1.y);
                bq[2] = f2tf(b1.z); bq[3] = f2tf(b1.w);
            }
        } else {
            Bs[0][nbK * BROW + nbN + 0] = f2tf(b0.x);
            Bs[0][nbK * BROW + nbN + 1] = f2tf(b0.y);
            Bs[0][nbK * BROW + nbN + 2] = f2tf(b0.z);
            Bs[0][nbK * BROW + nbN + 3] = f2tf(b0.w);
            if (BN == 128) {
                Bs[0][nbK * BROW + nbN + 64] = f2tf(b1.x);
                Bs[0][nbK * BROW + nbN + 65] = f2tf(b1.y);
                Bs[0][nbK * BROW + nbN + 66] = f2tf(b1.z);
                Bs[0][nbK * BROW + nbN + 67] = f2tf(b1.w);
            }
        }
    }
    __syncthreads();

    for (int kt = 0; kt < ntiles; kt++) {
        const int cur = kt & 1;
        const bool more = (kt + 1 < ntiles);
        if (more) {
            const int k0 = (kt + 1) * BK;
            const float* ap = A + (size_t)(bm + ar) * K + k0 + ak;
            a0 = *(const float4*)ap;
            a1 = *(const float4*)(ap + (size_t)64 * K);
            if (TRANSB) {
                int gn0 = bn + tbN;
                b0 = (gn0 < N) ? *(const float4*)(Bm + (size_t)gn0 * K + k0 + tbK)
                               : make_float4(0.f, 0.f, 0.f, 0.f);
                if (BN == 128) {
                    int gn1 = gn0 + 64;
                    b1 = (gn1 < N) ? *(const float4*)(Bm + (size_t)gn1 * K + k0 + tbK)
                                   : make_float4(0.f, 0.f, 0.f, 0.f);
                }
            } else {
                const float* bp = Bm + (size_t)(k0 + nbK) * N + bn + nbN;
                b0 = *(const float4*)bp;
                if (BN == 128) b1 = *(const float4*)(bp + 64);
            }
        }
#pragma unroll
        for (int ks = 0; ks < 2; ks++) {
            const int k8 = ks * 8;
            unsigned af[2][4], bf[NJ][2];
#pragma unroll
            for (int i = 0; i < 2; i++) {
                const int mr = wm + i * 16 + g;
                af[i][0] = As[cur][mr    ][k8 + t];
                af[i][1] = As[cur][mr + 8][k8 + t];
                af[i][2] = As[cur][mr    ][k8 + t + 4];
                af[i][3] = As[cur][mr + 8][k8 + t + 4];
            }
#pragma unroll
            for (int j = 0; j < NJ; j++) {
                const int nc = wn + j * 8 + g;
                if (TRANSB) {
                    bf[j][0] = Bs[cur][nc * 20 + k8 + t];
                    bf[j][1] = Bs[cur][nc * 20 + k8 + t + 4];
                } else {
                    bf[j][0] = Bs[cur][(k8 + t) * BROW + nc];
                    bf[j][1] = Bs[cur][(k8 + t + 4) * BROW + nc];
                }
            }
#pragma unroll
            for (int i = 0; i < 2; i++)
#pragma unroll
                for (int j = 0; j < NJ; j++)
                    mma_tf32(acc[i][j], af[i], bf[j]);
        }
        if (more) {
            const int nxt = cur ^ 1;
            As[nxt][ar][ak+0] = f2tf(a0.x); As[nxt][ar][ak+1] = f2tf(a0.y);
            As[nxt][ar][ak+2] = f2tf(a0.z); As[nxt][ar][ak+3] = f2tf(a0.w);
            As[nxt][ar+64][ak+0] = f2tf(a1.x); As[nxt][ar+64][ak+1] = f2tf(a1.y);
            As[nxt][ar+64][ak+2] = f2tf(a1.z); As[nxt][ar+64][ak+3] = f2tf(a1.w);
            if (TRANSB) {
                unsigned* bp = &Bs[nxt][tbN * 20 + tbK];
                bp[0] = f2tf(b0.x); bp[1] = f2tf(b0.y);
                bp[2] = f2tf(b0.z); bp[3] = f2tf(b0.w);
                if (BN == 128) {
                    unsigned* bq = &Bs[nxt][(tbN + 64) * 20 + tbK];
                    bq[0] = f2tf(b1.x); bq[1] = f2tf(b1.y);
                    bq[2] = f2tf(b1.z); bq[3] = f2tf(b1.w);
                }
            } else {
                Bs[nxt][nbK * BROW + nbN + 0] = f2tf(b0.x);
                Bs[nxt][nbK * BROW + nbN + 1] = f2tf(b0.y);
                Bs[nxt][nbK * BROW + nbN + 2] = f2tf(b0.z);
                Bs[nxt][nbK * BROW + nbN + 3] = f2tf(b0.w);
                if (BN == 128) {
                    Bs[nxt][nbK * BROW + nbN + 64] = f2tf(b1.x);
                    Bs[nxt][nbK * BROW + nbN + 65] = f2tf(b1.y);
                    Bs[nxt][nbK * BROW + nbN + 66] = f2tf(b1.z);
                    Bs[nxt][nbK * BROW + nbN + 67] = f2tf(b1.w);
                }
            }
        }
        __syncthreads();
    }

    // ---- epilogue ----
#pragma unroll
    for (int i = 0; i < 2; i++) {
        const int r0 = bm + wm + i * 16 + g;
        const int r1 = r0 + 8;
#pragma unroll
        for (int j = 0; j < NJ; j++) {
            const int c = bn + wn + j * 8 + 2 * t;
            float v00 = acc[i][j][0], v01 = acc[i][j][1];
            float v10 = acc[i][j][2], v11 = acc[i][j][3];
            if (EPI & 1) {
                float bb0 = bias[c], bb1 = bias[c + 1];
                v00 += bb0; v01 += bb1; v10 += bb0; v11 += bb1;
            }
            if (EPI & 2) {
                v00 = gelu_exact(v00); v01 = gelu_exact(v01);
                v10 = gelu_exact(v10); v11 = gelu_exact(v11);
            }
            if (EPI & 4) {
                const float* rp0 = resid + (size_t)r0 * N + c;
                const float* rp1 = resid + (size_t)r1 * N + c;
                v00 += rp0[0]; v01 += rp0[1];
                v10 += rp1[0]; v11 += rp1[1];
            }
            if (!TRANSB) {
                float2 p0; p0.x = v00; p0.y = v01;
                float2 p1; p1.x = v10; p1.y = v11;
                *(float2*)(C + (size_t)r0 * N + c) = p0;
                *(float2*)(C + (size_t)r1 * N + c) = p1;
            } else {
                // N may be odd (V=50257): scalar bounds-checked stores
                if (c < N)     { C[(size_t)r0 * N + c]     = v00; C[(size_t)r1 * N + c]     = v10; }
                if (c + 1 < N) { C[(size_t)r0 * N + c + 1] = v01; C[(size_t)r1 * N + c + 1] = v11; }
            }
        }
    }
}

template <int BN, bool TRANSB, int EPI>
__global__ __launch_bounds__(256)
void tgemm_k(const float* __restrict__ A, const float* __restrict__ Bm,
             const float* __restrict__ bias, const float* __restrict__ resid,
             float* __restrict__ C, int N, int K) {
    tgemm_dev<BN, TRANSB, EPI>(A, Bm, bias, resid, C, N, K,
                               blockIdx.x * 128, blockIdx.y * BN);
}

__global__ __launch_bounds__(256)
void qkv_k(const float* __restrict__ A,
           const float* __restrict__ Wq, const float* __restrict__ Wk,
           const float* __restrict__ Wv,
           float* __restrict__ q, float* __restrict__ k, float* __restrict__ v) {
    const float* Bm = (blockIdx.z == 0) ? Wq : (blockIdx.z == 1) ? Wk : Wv;
    float* C        = (blockIdx.z == 0) ? q  : (blockIdx.z == 1) ? k  : v;
    tgemm_dev<64, false, 0>(A, Bm, nullptr, nullptr, C, E_SZ, E_SZ,
                            blockIdx.x * 128, blockIdx.y * 64);
}

// ---------------- Causal attention: flash tile, fp32 register GEMMs --------
#define ATTN_SMEM (4 * 64 * 68 * 4 + 2 * 64 * 4)

__global__ __launch_bounds__(256)
void attn_kernel(const float* __restrict__ q, const float* __restrict__ k,
                 const float* __restrict__ v, float* __restrict__ o) {
    extern __shared__ float sm[];
    float (*Qs)[68] = (float(*)[68])(sm);
    float (*Ks)[68] = (float(*)[68])(sm + 64 * 68);
    float (*Vs)[68] = (float(*)[68])(sm + 2 * 64 * 68);
    float (*Ss)[68] = (float(*)[68])(sm + 3 * 64 * 68);
    float* ms = sm + 4 * 64 * 68;
    float* ls = ms + 64;

    const int bh  = blockIdx.y;
    const int b   = bh / H_SZ, h = bh % H_SZ;
    const int q0  = blockIdx.x * 64;
    const int tid = threadIdx.x;
    const int tx  = tid & 15, ty = tid >> 4;

#pragma unroll
    for (int i = 0; i < 4; i++) {
        int f  = tid + i * 256;
        int qq = f & 63, d4 = (f >> 6) * 4;
        float4 t = *(const float4*)(q + ((size_t)(b * T_SZ + q0 + qq) * E_SZ) + h * D_SZ + d4);
        Qs[d4+0][qq] = t.x * 0.125f; Qs[d4+1][qq] = t.y * 0.125f;
        Qs[d4+2][qq] = t.z * 0.125f; Qs[d4+3][qq] = t.w * 0.125f;
    }
    if (tid < 64) { ms[tid] = -1e30f; ls[tid] = 0.f; }

    float acc[4][4];
#pragma unroll
    for (int r = 0; r < 4; r++)
#pragma unroll
        for (int c = 0; c < 4; c++) acc[r][c] = 0.f;

    for (int kt = 0; kt <= q0; kt += 64) {
#pragma unroll
        for (int i = 0; i < 4; i++) {
            int f  = tid + i * 256;
            int kk = f & 63, d4 = (f >> 6) * 4;
            float4 t = *(const float4*)(k + ((size_t)(b * T_SZ + kt + kk) * E_SZ) + h * D_SZ + d4);
            Ks[d4+0][kk] = t.x; Ks[d4+1][kk] = t.y;
            Ks[d4+2][kk] = t.z; Ks[d4+3][kk] = t.w;
        }
#pragma unroll
        for (int i = 0; i < 4; i++) {
            int f  = tid + i * 256;
            int kk = f >> 4, d4 = (f & 15) * 4;
            *(float4*)&Vs[kk][d4] =
                *(const float4*)(v + ((size_t)(b * T_SZ + kt + kk) * E_SZ) + h * D_SZ + d4);
        }
        __syncthreads();

        // ---- S = Q K^T ----
        float s[4][4];
#pragma unroll
        for (int r = 0; r < 4; r++)
#pragma unroll
            for (int c = 0; c < 4; c++) s[r][c] = 0.f;
#pragma unroll 4
        for (int d = 0; d < 64; d++) {
            float4 aq = *(const float4*)&Qs[d][4 * ty];
            float4 bk = *(const float4*)&Ks[d][4 * tx];
            float a[4] = {aq.x, aq.y, aq.z, aq.w};
            float bb[4] = {bk.x, bk.y, bk.z, bk.w};
#pragma unroll
            for (int r = 0; r < 4; r++)
#pragma unroll
                for (int c = 0; c < 4; c++) s[r][c] += a[r] * bb[c];
        }

        // ---- softmax (row = half-warp) ----
        const bool diag = (kt == q0);
        float cfl[4];
#pragma unroll
        for (int r = 0; r < 4; r++) {
            const int row = 4 * ty + r;
            if (diag) {
#pragma unroll
                for (int c = 0; c < 4; c++)
                    if (4 * tx + c > row) s[r][c] = -1e30f;
            }
            float mx = fmaxf(fmaxf(s[r][0], s[r][1]), fmaxf(s[r][2], s[r][3]));
#pragma unroll
            for (int off = 1; off < 16; off <<= 1)
                mx = fmaxf(mx, __shfl_xor_sync(0xffffffffu, mx, off));
            const float mold = ms[row];
            const float mnew = fmaxf(mold, mx);
            float ps = 0.f;
#pragma unroll
            for (int c = 0; c < 4; c++) {
                float p = __expf(s[r][c] - mnew);
                Ss[row][4 * tx + c] = p;
                ps += p;
            }
#pragma unroll
            for (int off = 1; off < 16; off <<= 1)
                ps += __shfl_xor_sync(0xffffffffu, ps, off);
            cfl[r] = __expf(mold - mnew);
            if (tx == 0) { ms[row] = mnew; ls[row] = ls[row] * cfl[r] + ps; }
        }
        __syncthreads();

        // ---- O = O*cf + P V (vectorized over kk: 0.5 B/FMA from smem) ----
#pragma unroll
        for (int r = 0; r < 4; r++)
#pragma unroll
            for (int c = 0; c < 4; c++) acc[r][c] *= cfl[r];
#pragma unroll 2
        for (int kk = 0; kk < 64; kk += 4) {
            float4 p[4];
#pragma unroll
            for (int r = 0; r < 4; r++)
                p[r] = *(const float4*)&Ss[4 * ty + r][kk];
            float4 v0 = *(const float4*)&Vs[kk    ][4 * tx];
            float4 v1 = *(const float4*)&Vs[kk + 1][4 * tx];
            float4 v2 = *(const float4*)&Vs[kk + 2][4 * tx];
            float4 v3 = *(const float4*)&Vs[kk + 3][4 * tx];
#pragma unroll
            for (int r = 0; r < 4; r++) {
                acc[r][0] += p[r].x * v0.x + p[r].y * v1.x + p[r].z * v2.x + p[r].w * v3.x;
                acc[r][1] += p[r].x * v0.y + p[r].y * v1.y + p[r].z * v2.y + p[r].w * v3.y;
                acc[r][2] += p[r].x * v0.z + p[r].y * v1.z + p[r].z * v2.z + p[r].w * v3.z;
                acc[r][3] += p[r].x * v0.w + p[r].y * v1.w + p[r].z * v2.w + p[r].w * v3.w;
            }
        }
        __syncthreads();
    }

#pragma unroll
    for (int r = 0; r < 4; r++) {
        const float inv = 1.f / ls[4 * ty + r];
        float4 t;
        t.x = acc[r][0] * inv; t.y = acc[r][1] * inv;
        t.z = acc[r][2] * inv; t.w = acc[r][3] * inv;
        *(float4*)(o + ((size_t)(b * T_SZ + q0 + 4 * ty + r) * E_SZ) + h * D_SZ + 4 * tx) = t;
    }
}

// ---------------- Host orchestration ----------------
extern "C" void kernel_launch(void* const* d_in, const int* in_sizes, int n_in,
                              void* d_out, int out_size) {
    (void)in_sizes; (void)n_in; (void)out_size;
    const int*   tokens = (const int*)  d_in[0];
    const float* wte    = (const float*)d_in[1];
    const float* wpe    = (const float*)d_in[2];
    const float* Wq     = (const float*)d_in[3];
    const float* Wk     = (const float*)d_in[4];
    const float* Wv     = (const float*)d_in[5];
    const float* Wo     = (const float*)d_in[6];
    const float* bo     = (const float*)d_in[7];
    const float* ln1_s  = (const float*)d_in[8];
    const float* ln1_b  = (const float*)d_in[9];
    const float* W1     = (const float*)d_in[10];
    const float* b1     = (const float*)d_in[11];
    const float* W2     = (const float*)d_in[12];
    const float* b2     = (const float*)d_in[13];
    const float* ln2_s  = (const float*)d_in[14];
    const float* ln2_b  = (const float*)d_in[15];
    const float* lnf_s  = (const float*)d_in[16];
    const float* lnf_b  = (const float*)d_in[17];
    float* out = (float*)d_out;

    float *x, *h, *q, *k, *v, *att, *m1;
    cudaGetSymbolAddress((void**)&x,   g_x);
    cudaGetSymbolAddress((void**)&h,   g_h);
    cudaGetSymbolAddress((void**)&q,   g_q);
    cudaGetSymbolAddress((void**)&k,   g_k);
    cudaGetSymbolAddress((void**)&v,   g_v);
    cudaGetSymbolAddress((void**)&att, g_att);
    cudaGetSymbolAddress((void**)&m1,  g_m1);

    cudaFuncSetAttribute(attn_kernel,
                         cudaFuncAttributeMaxDynamicSharedMemorySize, ATTN_SMEM);

    embed_kernel<<<BT, 192>>>(tokens, wte, wpe, x);

    // grid: x = m-blocks (16), y = n-blocks
    const dim3 gE(BT / 128, E_SZ / 64);            // 16 x 12
    const dim3 gQKV(BT / 128, E_SZ / 64, 3);       // 16 x 12 x 3
    const dim3 gF(BT / 128, FF / 128);             // 16 x 24
    const dim3 gATT(T_SZ / 64, B_SZ * H_SZ);       // 16 x 24
    const dim3 gLOG(BT / 128, (V_SZ + 127) / 128); // 16 x 393

    for (int l = 0; l < L_SZ; l++) {
        const size_t wOff  = (size_t)l * E_SZ * E_SZ;
        const size_t w1Off = (size_t)l * E_SZ * FF;
        const size_t vOff  = (size_t)l * E_SZ;
        const size_t fOff  = (size_t)l * FF;

        layernorm_kernel<<<BT, 256>>>(x, ln1_s + vOff, ln1_b + vOff, h);
        qkv_k<<<gQKV, 256>>>(h, Wq + wOff, Wk + wOff, Wv + wOff, q, k, v);
        attn_kernel<<<gATT, 256, ATTN_SMEM>>>(q, k, v, att);
        tgemm_k<64, false, 5><<<gE, 256>>>(att, Wo + wOff, bo + vOff, x, x, E_SZ, E_SZ);
        layernorm_kernel<<<BT, 256>>>(x, ln2_s + vOff, ln2_b + vOff, h);
        tgemm_k<128, false, 3><<<gF, 256>>>(h, W1 + w1Off, b1 + fOff, nullptr, m1, FF, E_SZ);
        tgemm_k<64, false, 5><<<gE, 256>>>(m1, W2 + w1Off, b2 + vOff, x, x, E_SZ, FF);
    }

    layernorm_kernel<<<BT, 256>>>(x, lnf_s, lnf_b, h);
    tgemm_k<128, true, 0><<<gLOG, 256>>>(h, wte, nullptr, nullptr, out, V_SZ, E_SZ);
}

// round 8
// speedup vs baseline: 3.2101x; 1.1715x over previous
#include <cuda_runtime.h>
#include <cuda_bf16.h>
#include <math.h>

// ---------------- Problem constants ----------------
#define V_SZ 50257
#define E_SZ 768
#define H_SZ 12
#define L_SZ 6
#define T_SZ 1024
#define B_SZ 2
#define D_SZ 64
#define BT   (B_SZ * T_SZ)      // 2048
#define FF   (4 * E_SZ)         // 3072

// ---------------- Scratch (device globals; no allocations allowed) ----------
__device__ float g_x  [BT * E_SZ];
__device__ float g_h  [BT * E_SZ];
__device__ float g_q  [BT * E_SZ];
__device__ float g_k  [BT * E_SZ];
__device__ float g_v  [BT * E_SZ];
__device__ float g_att[BT * E_SZ];
__device__ float g_m1 [BT * FF];
// tf32-rounded weight copies
__device__ float g_wq [L_SZ * E_SZ * E_SZ];
__device__ float g_wk [L_SZ * E_SZ * E_SZ];
__device__ float g_wv [L_SZ * E_SZ * E_SZ];
__device__ float g_wo [L_SZ * E_SZ * E_SZ];
__device__ float g_w1 [L_SZ * E_SZ * FF];
__device__ float g_w2 [L_SZ * E_SZ * FF];
__device__ float g_wte[V_SZ * E_SZ];

// ---------------- tf32 helpers ----------------
__device__ __forceinline__ unsigned f2tf(float f) {
    unsigned u;
    asm("cvt.rna.tf32.f32 %0, %1;" : "=r"(u) : "f"(f));
    return u;
}
__device__ __forceinline__ float rtf(float f) { return __uint_as_float(f2tf(f)); }

// round-convert fp32 array to tf32-representable fp32
__global__ void cvt_kernel(const float4* __restrict__ src, float4* __restrict__ dst, int n4) {
    int i = blockIdx.x * 256 + threadIdx.x;
    if (i < n4) {
        float4 v = src[i];
        v.x = rtf(v.x); v.y = rtf(v.y); v.z = rtf(v.z); v.w = rtf(v.w);
        dst[i] = v;
    }
}

// ---------------- Embedding ----------------
__global__ void embed_kernel(const int* __restrict__ tok,
                             const float* __restrict__ wte,
                             const float* __restrict__ wpe,
                             float* __restrict__ x) {
    int row = blockIdx.x;
    int t   = row % T_SZ;
    int tk  = tok[row];
    int e   = threadIdx.x * 4;
    const float4 a = *(const float4*)(wte + (size_t)tk * E_SZ + e);
    const float4 b = *(const float4*)(wpe + (size_t)t  * E_SZ + e);
    float4 o;
    o.x = a.x + b.x; o.y = a.y + b.y; o.z = a.z + b.z; o.w = a.w + b.w;
    *(float4*)(x + (size_t)row * E_SZ + e) = o;
}

// ---------------- LayerNorm (emits tf32-rounded output) ----------------
__global__ void layernorm_kernel(const float* __restrict__ x,
                                 const float* __restrict__ sc,
                                 const float* __restrict__ bi,
                                 float* __restrict__ out) {
    int row = blockIdx.x;
    const float* xr = x + (size_t)row * E_SZ;
    float lv[3];
    float s = 0.f, sq = 0.f;
#pragma unroll
    for (int i = 0; i < 3; i++) {
        float t = xr[threadIdx.x + i * 256];
        lv[i] = t; s += t; sq += t * t;
    }
#pragma unroll
    for (int o = 16; o > 0; o >>= 1) {
        s  += __shfl_down_sync(0xffffffffu, s,  o);
        sq += __shfl_down_sync(0xffffffffu, sq, o);
    }
    __shared__ float sa[8], sb[8];
    int w = threadIdx.x >> 5, lane = threadIdx.x & 31;
    if (lane == 0) { sa[w] = s; sb[w] = sq; }
    __syncthreads();
    __shared__ float s_mu, s_rstd;
    if (threadIdx.x == 0) {
        float ts = 0.f, tq = 0.f;
#pragma unroll
        for (int i = 0; i < 8; i++) { ts += sa[i]; tq += sb[i]; }
        float mu  = ts * (1.0f / E_SZ);
        float var = tq * (1.0f / E_SZ) - mu * mu;
        s_mu = mu;
        s_rstd = rsqrtf(var + 1e-5f);
    }
    __syncthreads();
    float mu = s_mu, rstd = s_rstd;
#pragma unroll
    for (int i = 0; i < 3; i++) {
        int c = threadIdx.x + i * 256;
        out[(size_t)row * E_SZ + c] = rtf((lv[i] - mu) * rstd * sc[c] + bi[c]);
    }
}

// ---------------- cp.async helpers ----------------
__device__ __forceinline__ void cp16(unsigned sdst, const void* src, bool pred) {
    int sz = pred ? 16 : 0;
    asm volatile("cp.async.cg.shared.global [%0], [%1], 16, %2;\n"
                 :: "r"(sdst), "l"(src), "r"(sz));
}
__device__ __forceinline__ void cp_commit() {
    asm volatile("cp.async.commit_group;\n");
}
__device__ __forceinline__ void cp_wait1() {
    asm volatile("cp.async.wait_group 1;\n");
}

// ---------------- TF32 tensor-core GEMM, cp.async 3-stage ----------------
// BM=128, BN=64/128, BK=16. 8 warps: 4(m) x 2(n); warp tile 32 x (BN/2).
// Inputs must be tf32-rounded fp32 (raw bits feed the MMA unchanged).
// EPI bit0: +bias; bit1: GELU; bit2: +resid; bit3: round output to tf32
__device__ __forceinline__ float gelu_exact(float v) {
    return 0.5f * v * (1.0f + erff(v * 0.70710678118654752f));
}
__device__ __forceinline__ void mma_tf32(float* d, const unsigned* a, const unsigned* b) {
    asm volatile(
        "mma.sync.aligned.m16n8k8.row.col.f32.tf32.tf32.f32 "
        "{%0,%1,%2,%3}, {%4,%5,%6,%7}, {%8,%9}, {%0,%1,%2,%3};"
        : "+f"(d[0]), "+f"(d[1]), "+f"(d[2]), "+f"(d[3])
        : "r"(a[0]), "r"(a[1]), "r"(a[2]), "r"(a[3]), "r"(b[0]), "r"(b[1]));
}

template <int BN, bool TRANSB, int EPI>
__device__ __forceinline__
void tgemm_dev(const float* __restrict__ A, const float* __restrict__ Bm,
               const float* __restrict__ bias, const float* __restrict__ resid,
               float* __restrict__ C, int N, int K, int bm, int bn) {
    constexpr int BK   = 16;
    constexpr int NJ   = BN / 16;
    constexpr int BROW = BN + 4;                         // non-trans B stride
    constexpr int ASZ  = 128 * 20;                       // unsigneds / stage
    constexpr int BSZ  = TRANSB ? (BN * 20) : (BK * BROW);

    extern __shared__ unsigned smem_u[];
    unsigned* sA = smem_u;                // 3 stages
    unsigned* sB = smem_u + 3 * ASZ;      // 3 stages

    const int tid  = threadIdx.x;
    const int lane = tid & 31;
    const int wid  = tid >> 5;
    const int wm   = (wid & 3) * 32;
    const int wn   = (wid >> 2) * (BN / 2);
    const int g    = lane >> 2;
    const int t    = lane & 3;

    float acc[2][NJ][4];
#pragma unroll
    for (int i = 0; i < 2; i++)
#pragma unroll
        for (int j = 0; j < NJ; j++)
#pragma unroll
            for (int r = 0; r < 4; r++) acc[i][j][r] = 0.f;

    // staging indices (float4 granularity)
    const int ar = tid >> 2;             // A rows ar, ar+64
    const int ak = (tid & 3) * 4;
    const int nbR = (BN == 128) ? (tid >> 5) : (tid >> 4);   // non-trans B k-row
    const int nbC = (BN == 128) ? ((tid & 31) * 4) : ((tid & 15) * 4);
    const int tbN = tid >> 2;            // trans B rows tbN (+64 if BN=128)
    const int tbK = (tid & 3) * 4;

    const unsigned sAaddr = (unsigned)__cvta_generic_to_shared(sA);
    const unsigned sBaddr = (unsigned)__cvta_generic_to_shared(sB);

    const int ntiles = K / BK;

    // ---- issue loads for tile kt into stage st ----
    auto issue = [&](int st, int kt) {
        const int k0 = kt * BK;
        unsigned a_s = sAaddr + (st * ASZ) * 4;
        unsigned b_s = sBaddr + (st * BSZ) * 4;
        const float* ap = A + (size_t)(bm + ar) * K + k0 + ak;
        cp16(a_s + (ar * 20 + ak) * 4,        ap,                true);
        cp16(a_s + ((ar + 64) * 20 + ak) * 4, ap + (size_t)64 * K, true);
        if (TRANSB) {
            int gn0 = bn + tbN;
            const float* bp0 = Bm + (size_t)(gn0 < N ? gn0 : 0) * K + k0 + tbK;
            cp16(b_s + (tbN * 20 + tbK) * 4, bp0, gn0 < N);
            if (BN == 128) {
                int gn1 = gn0 + 64;
                const float* bp1 = Bm + (size_t)(gn1 < N ? gn1 : 0) * K + k0 + tbK;
                cp16(b_s + ((tbN + 64) * 20 + tbK) * 4, bp1, gn1 < N);
            }
        } else {
            const float* bp = Bm + (size_t)(k0 + nbR) * N + bn + nbC;
            cp16(b_s + (nbR * BROW + nbC) * 4, bp, true);
            if (BN == 128)
                cp16(b_s + ((nbR + 8) * BROW + nbC) * 4, bp + (size_t)8 * N, true);
        }
    };

    issue(0, 0); cp_commit();
    issue(1, 1); cp_commit();

    for (int kt = 0; kt < ntiles; kt++) {
        cp_wait1();
        __syncthreads();
        const int cur = kt % 3;
        const unsigned* As = sA + cur * ASZ;
        const unsigned* Bs = sB + cur * BSZ;
#pragma unroll
        for (int ks = 0; ks < 2; ks++) {
            const int k8 = ks * 8;
            unsigned af[2][4], bf[NJ][2];
#pragma unroll
            for (int i = 0; i < 2; i++) {
                const int mr = wm + i * 16 + g;
                af[i][0] = As[mr * 20 + k8 + t];
                af[i][1] = As[(mr + 8) * 20 + k8 + t];
                af[i][2] = As[mr * 20 + k8 + t + 4];
                af[i][3] = As[(mr + 8) * 20 + k8 + t + 4];
            }
#pragma unroll
            for (int j = 0; j < NJ; j++) {
                const int nc = wn + j * 8 + g;
                if (TRANSB) {
                    bf[j][0] = Bs[nc * 20 + k8 + t];
                    bf[j][1] = Bs[nc * 20 + k8 + t + 4];
                } else {
                    bf[j][0] = Bs[(k8 + t) * BROW + nc];
                    bf[j][1] = Bs[(k8 + t + 4) * BROW + nc];
                }
            }
#pragma unroll
            for (int i = 0; i < 2; i++)
#pragma unroll
                for (int j = 0; j < NJ; j++)
                    mma_tf32(acc[i][j], af[i], bf[j]);
        }
        if (kt + 2 < ntiles) issue((kt + 2) % 3, kt + 2);
        cp_commit();
    }

    // ---- epilogue ----
#pragma unroll
    for (int i = 0; i < 2; i++) {
        const int r0 = bm + wm + i * 16 + g;
        const int r1 = r0 + 8;
#pragma unroll
        for (int j = 0; j < NJ; j++) {
            const int c = bn + wn + j * 8 + 2 * t;
            float v00 = acc[i][j][0], v01 = acc[i][j][1];
            float v10 = acc[i][j][2], v11 = acc[i][j][3];
            if (EPI & 1) {
                float bb0 = bias[c], bb1 = bias[c + 1];
                v00 += bb0; v01 += bb1; v10 += bb0; v11 += bb1;
            }
            if (EPI & 2) {
                v00 = gelu_exact(v00); v01 = gelu_exact(v01);
                v10 = gelu_exact(v10); v11 = gelu_exact(v11);
            }
            if (EPI & 4) {
                const float* rp0 = resid + (size_t)r0 * N + c;
                const float* rp1 = resid + (size_t)r1 * N + c;
                v00 += rp0[0]; v01 += rp0[1];
                v10 += rp1[0]; v11 += rp1[1];
            }
            if (EPI & 8) {
                v00 = rtf(v00); v01 = rtf(v01);
                v10 = rtf(v10); v11 = rtf(v11);
            }
            if (!TRANSB) {
                float2 p0; p0.x = v00; p0.y = v01;
                float2 p1; p1.x = v10; p1.y = v11;
                *(float2*)(C + (size_t)r0 * N + c) = p0;
                *(float2*)(C + (size_t)r1 * N + c) = p1;
            } else {
                // N may be odd (V=50257): scalar bounds-checked stores
                if (c < N)     { C[(size_t)r0 * N + c]     = v00; C[(size_t)r1 * N + c]     = v10; }
                if (c + 1 < N) { C[(size_t)r0 * N + c + 1] = v01; C[(size_t)r1 * N + c + 1] = v11; }
            }
        }
    }
}

template <int BN, bool TRANSB, int EPI>
__global__ __launch_bounds__(256)
void tgemm_k(const float* __restrict__ A, const float* __restrict__ Bm,
             const float* __restrict__ bias, const float* __restrict__ resid,
             float* __restrict__ C, int N, int K) {
    tgemm_dev<BN, TRANSB, EPI>(A, Bm, bias, resid, C, N, K,
                               blockIdx.x * 128, blockIdx.y * BN);
}

__global__ __launch_bounds__(256)
void qkv_k(const float* __restrict__ A,
           const float* __restrict__ Wq, const float* __restrict__ Wk,
           const float* __restrict__ Wv,
           float* __restrict__ q, float* __restrict__ k, float* __restrict__ v) {
    const float* Bm = (blockIdx.z == 0) ? Wq : (blockIdx.z == 1) ? Wk : Wv;
    float* C        = (blockIdx.z == 0) ? q  : (blockIdx.z == 1) ? k  : v;
    tgemm_dev<64, false, 0>(A, Bm, nullptr, nullptr, C, E_SZ, E_SZ,
                            blockIdx.x * 128, blockIdx.y * 64);
}

// smem bytes per instantiation (3 stages)
#define SM_G64F  (3 * (128 * 20 + 16 * 68) * 4)    // 43776
#define SM_G128F (3 * (128 * 20 + 16 * 132) * 4)   // 56064
#define SM_G128T (3 * (128 * 20 + 128 * 20) * 4)   // 61440

// ---------------- Causal attention: flash tile, fp32 register GEMMs --------
#define ATTN_SMEM (4 * 64 * 68 * 4 + 2 * 64 * 4)

__global__ __launch_bounds__(256)
void attn_kernel(const float* __restrict__ q, const float* __restrict__ k,
                 const float* __restrict__ v, float* __restrict__ o) {
    extern __shared__ float sm[];
    float (*Qs)[68] = (float(*)[68])(sm);
    float (*Ks)[68] = (float(*)[68])(sm + 64 * 68);
    float (*Vs)[68] = (float(*)[68])(sm + 2 * 64 * 68);
    float (*Ss)[68] = (float(*)[68])(sm + 3 * 64 * 68);
    float* ms = sm + 4 * 64 * 68;
    float* ls = ms + 64;

    const int bh  = blockIdx.y;
    const int b   = bh / H_SZ, h = bh % H_SZ;
    const int q0  = blockIdx.x * 64;
    const int tid = threadIdx.x;
    const int tx  = tid & 15, ty = tid >> 4;

#pragma unroll
    for (int i = 0; i < 4; i++) {
        int f  = tid + i * 256;
        int qq = f & 63, d4 = (f >> 6) * 4;
        float4 t = *(const float4*)(q + ((size_t)(b * T_SZ + q0 + qq) * E_SZ) + h * D_SZ + d4);
        Qs[d4+0][qq] = t.x * 0.125f; Qs[d4+1][qq] = t.y * 0.125f;
        Qs[d4+2][qq] = t.z * 0.125f; Qs[d4+3][qq] = t.w * 0.125f;
    }
    if (tid < 64) { ms[tid] = -1e30f; ls[tid] = 0.f; }

    float acc[4][4];
#pragma unroll
    for (int r = 0; r < 4; r++)
#pragma unroll
        for (int c = 0; c < 4; c++) acc[r][c] = 0.f;

    for (int kt = 0; kt <= q0; kt += 64) {
#pragma unroll
        for (int i = 0; i < 4; i++) {
            int f  = tid + i * 256;
            int kk = f & 63, d4 = (f >> 6) * 4;
            float4 t = *(const float4*)(k + ((size_t)(b * T_SZ + kt + kk) * E_SZ) + h * D_SZ + d4);
            Ks[d4+0][kk] = t.x; Ks[d4+1][kk] = t.y;
            Ks[d4+2][kk] = t.z; Ks[d4+3][kk] = t.w;
        }
#pragma unroll
        for (int i = 0; i < 4; i++) {
            int f  = tid + i * 256;
            int kk = f >> 4, d4 = (f & 15) * 4;
            *(float4*)&Vs[kk][d4] =
                *(const float4*)(v + ((size_t)(b * T_SZ + kt + kk) * E_SZ) + h * D_SZ + d4);
        }
        __syncthreads();

        // ---- S = Q K^T ----
        float s[4][4];
#pragma unroll
        for (int r = 0; r < 4; r++)
#pragma unroll
            for (int c = 0; c < 4; c++) s[r][c] = 0.f;
#pragma unroll 4
        for (int d = 0; d < 64; d++) {
            float4 aq = *(const float4*)&Qs[d][4 * ty];
            float4 bk = *(const float4*)&Ks[d][4 * tx];
            float a[4] = {aq.x, aq.y, aq.z, aq.w};
            float bb[4] = {bk.x, bk.y, bk.z, bk.w};
#pragma unroll
            for (int r = 0; r < 4; r++)
#pragma unroll
                for (int c = 0; c < 4; c++) s[r][c] += a[r] * bb[c];
        }

        // ---- softmax (row = half-warp) ----
        const bool diag = (kt == q0);
        float cfl[4];
#pragma unroll
        for (int r = 0; r < 4; r++) {
            const int row = 4 * ty + r;
            if (diag) {
#pragma unroll
                for (int c = 0; c < 4; c++)
                    if (4 * tx + c > row) s[r][c] = -1e30f;
            }
            float mx = fmaxf(fmaxf(s[r][0], s[r][1]), fmaxf(s[r][2], s[r][3]));
#pragma unroll
            for (int off = 1; off < 16; off <<= 1)
                mx = fmaxf(mx, __shfl_xor_sync(0xffffffffu, mx, off));
            const float mold = ms[row];
            const float mnew = fmaxf(mold, mx);
            float ps = 0.f;
#pragma unroll
            for (int c = 0; c < 4; c++) {
                float p = __expf(s[r][c] - mnew);
                Ss[row][4 * tx + c] = p;
                ps += p;
            }
#pragma unroll
            for (int off = 1; off < 16; off <<= 1)
                ps += __shfl_xor_sync(0xffffffffu, ps, off);
            cfl[r] = __expf(mold - mnew);
            if (tx == 0) { ms[row] = mnew; ls[row] = ls[row] * cfl[r] + ps; }
        }
        __syncthreads();

        // ---- O = O*cf + P V (scalar Ss reads; round-6 form) ----
#pragma unroll
        for (int r = 0; r < 4; r++)
#pragma unroll
            for (int c = 0; c < 4; c++) acc[r][c] *= cfl[r];
#pragma unroll 4
        for (int kk = 0; kk < 64; kk++) {
            float4 vv = *(const float4*)&Vs[kk][4 * tx];
#pragma unroll
            for (int r = 0; r < 4; r++) {
                float p = Ss[4 * ty + r][kk];
                acc[r][0] += p * vv.x; acc[r][1] += p * vv.y;
                acc[r][2] += p * vv.z; acc[r][3] += p * vv.w;
            }
        }
        __syncthreads();
    }

    // ---- epilogue: tf32-rounded output (A operand of proj GEMM) ----
#pragma unroll
    for (int r = 0; r < 4; r++) {
        const float inv = 1.f / ls[4 * ty + r];
        float4 t;
        t.x = rtf(acc[r][0] * inv); t.y = rtf(acc[r][1] * inv);
        t.z = rtf(acc[r][2] * inv); t.w = rtf(acc[r][3] * inv);
        *(float4*)(o + ((size_t)(b * T_SZ + q0 + 4 * ty + r) * E_SZ) + h * D_SZ + 4 * tx) = t;
    }
}

// ---------------- Host orchestration ----------------
extern "C" void kernel_launch(void* const* d_in, const int* in_sizes, int n_in,
                              void* d_out, int out_size) {
    (void)in_sizes; (void)n_in; (void)out_size;
    const int*   tokens = (const int*)  d_in[0];
    const float* wte    = (const float*)d_in[1];
    const float* wpe    = (const float*)d_in[2];
    const float* Wq     = (const float*)d_in[3];
    const float* Wk     = (const float*)d_in[4];
    const float* Wv     = (const float*)d_in[5];
    const float* Wo     = (const float*)d_in[6];
    const float* bo     = (const float*)d_in[7];
    const float* ln1_s  = (const float*)d_in[8];
    const float* ln1_b  = (const float*)d_in[9];
    const float* W1     = (const float*)d_in[10];
    const float* b1     = (const float*)d_in[11];
    const float* W2     = (const float*)d_in[12];
    const float* b2     = (const float*)d_in[13];
    const float* ln2_s  = (const float*)d_in[14];
    const float* ln2_b  = (const float*)d_in[15];
    const float* lnf_s  = (const float*)d_in[16];
    const float* lnf_b  = (const float*)d_in[17];
    float* out = (float*)d_out;

    float *x, *h, *q, *k, *v, *att, *m1;
    float *wq, *wk, *wv, *wo, *w1, *w2, *wt;
    cudaGetSymbolAddress((void**)&x,   g_x);
    cudaGetSymbolAddress((void**)&h,   g_h);
    cudaGetSymbolAddress((void**)&q,   g_q);
    cudaGetSymbolAddress((void**)&k,   g_k);
    cudaGetSymbolAddress((void**)&v,   g_v);
    cudaGetSymbolAddress((void**)&att, g_att);
    cudaGetSymbolAddress((void**)&m1,  g_m1);
    cudaGetSymbolAddress((void**)&wq,  g_wq);
    cudaGetSymbolAddress((void**)&wk,  g_wk);
    cudaGetSymbolAddress((void**)&wv,  g_wv);
    cudaGetSymbolAddress((void**)&wo,  g_wo);
    cudaGetSymbolAddress((void**)&w1,  g_w1);
    cudaGetSymbolAddress((void**)&w2,  g_w2);
    cudaGetSymbolAddress((void**)&wt,  g_wte);

    cudaFuncSetAttribute(attn_kernel,
                         cudaFuncAttributeMaxDynamicSharedMemorySize, ATTN_SMEM);
    cudaFuncSetAttribute(tgemm_k<64, false, 5>,
                         cudaFuncAttributeMaxDynamicSharedMemorySize, SM_G64F);
    cudaFuncSetAttribute(tgemm_k<128, false, 11>,
                         cudaFuncAttributeMaxDynamicSharedMemorySize, SM_G128F);
    cudaFuncSetAttribute(tgemm_k<128, true, 0>,
                         cudaFuncAttributeMaxDynamicSharedMemorySize, SM_G128T);
    cudaFuncSetAttribute(qkv_k,
                         cudaFuncAttributeMaxDynamicSharedMemorySize, SM_G64F);

    // ---- per-launch weight rounding to tf32 ----
    {
        const int nE = L_SZ * E_SZ * E_SZ / 4;   // 884736
        const int nF = L_SZ * E_SZ * FF / 4;     // 3538944
        const int nV = V_SZ * E_SZ / 4;          // 9649344
        cvt_kernel<<<(nE + 255) / 256, 256>>>((const float4*)Wq, (float4*)wq, nE);
        cvt_kernel<<<(nE + 255) / 256, 256>>>((const float4*)Wk, (float4*)wk, nE);
        cvt_kernel<<<(nE + 255) / 256, 256>>>((const float4*)Wv, (float4*)wv, nE);
        cvt_kernel<<<(nE + 255) / 256, 256>>>((const float4*)Wo, (float4*)wo, nE);
        cvt_kernel<<<(nF + 255) / 256, 256>>>((const float4*)W1, (float4*)w1, nF);
        cvt_kernel<<<(nF + 255) / 256, 256>>>((const float4*)W2, (float4*)w2, nF);
        cvt_kernel<<<(nV + 255) / 256, 256>>>((const float4*)wte, (float4*)wt, nV);
    }

    embed_kernel<<<BT, 192>>>(tokens, wte, wpe, x);

    const dim3 gE(BT / 128, E_SZ / 64);            // 16 x 12
    const dim3 gQKV(BT / 128, E_SZ / 64, 3);       // 16 x 12 x 3
    const dim3 gF(BT / 128, FF / 128);             // 16 x 24
    const dim3 gATT(T_SZ / 64, B_SZ * H_SZ);       // 16 x 24
    const dim3 gLOG(BT / 128, (V_SZ + 127) / 128); // 16 x 393

    for (int l = 0; l < L_SZ; l++) {
        const size_t wOff  = (size_t)l * E_SZ * E_SZ;
        const size_t w1Off = (size_t)l * E_SZ * FF;
        const size_t vOff  = (size_t)l * E_SZ;
        const size_t fOff  = (size_t)l * FF;

        layernorm_kernel<<<BT, 256>>>(x, ln1_s + vOff, ln1_b + vOff, h);
        qkv_k<<<gQKV, 256, SM_G64F>>>(h, wq + wOff, wk + wOff, wv + wOff, q, k, v);
        attn_kernel<<<gATT, 256, ATTN_SMEM>>>(q, k, v, att);
        tgemm_k<64, false, 5><<<gE, 256, SM_G64F>>>(att, wo + wOff, bo + vOff, x, x, E_SZ, E_SZ);
        layernorm_kernel<<<BT, 256>>>(x, ln2_s + vOff, ln2_b + vOff, h);
        tgemm_k<128, false, 11><<<gF, 256, SM_G128F>>>(h, w1 + w1Off, b1 + fOff, nullptr, m1, FF, E_SZ);
        tgemm_k<64, false, 5><<<gE, 256, SM_G64F>>>(m1, w2 + w1Off, b2 + vOff, x, x, E_SZ, FF);
    }

    layernorm_kernel<<<BT, 256>>>(x, lnf_s, lnf_b, h);
    tgemm_k<128, true, 0><<<gLOG, 256, SM_G128T>>>(h, wt, nullptr, nullptr, out, V_SZ, E_SZ);
}